// round 9
// baseline (speedup 1.0000x reference)
#include <cuda_runtime.h>
#include <cuda_fp16.h>
#include <math.h>
#include <stdint.h>

// Problem constants
#define TT   4096
#define DD   1024
#define EE   16
#define CC   512
#define II   4096
#define IIS  2048

#define BK   32     // k-tile (elements)
#define HS   40     // A smem row stride in halves (32 data + 8 pad)
#define FS   36     // B smem row stride in floats (32 data + 4 pad)

// dynamic smem layouts (bytes)
// in : As[2][128][HS] fp16 (20480) + Gs[2][64][FS] fp32 (18432) + Us (18432) = 57344
// dn : As[2][128][HS] fp16 (20480) + Bs[2][128][FS] fp32 (36864)            = 57344
#define SM_IN_BYTES 57344
#define SM_DN_BYTES 57344

// ---------------- scratch (device globals; no allocs allowed) --------------
__device__ __align__(16) float g_scores[EE * TT];
__device__ int   g_tidx[EE * CC];
__device__ float g_tw  [EE * CC];
__device__ __align__(16) __half g_hxg[(size_t)EE * CC * DD];   // gathered tokens fp16
__device__ __align__(16) __half g_hH [(size_t)EE * CC * II];   // expert hidden fp16
__device__ __align__(16) __half g_hHs[(size_t)TT * IIS];       // shared hidden fp16
__device__ __align__(16) __half g_hx [(size_t)TT * DD];        // x fp16

// ---------------- helpers --------------------------------------------------
__device__ __forceinline__ void mma_f16(float* d, const unsigned* a, const unsigned* b,
                                        const float* c) {
    asm volatile(
        "mma.sync.aligned.m16n8k16.row.col.f32.f16.f16.f32 "
        "{%0,%1,%2,%3},{%4,%5,%6,%7},{%8,%9},{%10,%11,%12,%13};"
        : "=f"(d[0]), "=f"(d[1]), "=f"(d[2]), "=f"(d[3])
        : "r"(a[0]), "r"(a[1]), "r"(a[2]), "r"(a[3]),
          "r"(b[0]), "r"(b[1]),
          "f"(c[0]), "f"(c[1]), "f"(c[2]), "f"(c[3]));
}
__device__ __forceinline__ void cpa16(void* dst, const void* src) {
    unsigned s = (unsigned)__cvta_generic_to_shared(dst);
    asm volatile("cp.async.cg.shared.global [%0], [%1], 16;" :: "r"(s), "l"(src));
}
__device__ __forceinline__ void cpa_commit() { asm volatile("cp.async.commit_group;"); }
__device__ __forceinline__ void cpa_wait1()  { asm volatile("cp.async.wait_group 1;"); }

__device__ __forceinline__ unsigned ldh2(const __half* p) { return *(const unsigned*)p; }
__device__ __forceinline__ unsigned packh2(float a, float b) {
    __half2 h = __floats2half2_rn(a, b);
    return *(unsigned*)&h;
}
__device__ __forceinline__ float gelu_exact(float g) {
    return 0.5f * g * (1.f + erff(g * 0.70710678118654752f));
}

// ---------------- fp32 -> fp16 copy (x only) -------------------------------
__global__ void k_cvt_h(const float4* __restrict__ s, uint2* __restrict__ d, int n4) {
    for (int i = blockIdx.x * blockDim.x + threadIdx.x; i < n4; i += gridDim.x * blockDim.x) {
        float4 v = s[i];
        uint2 o; o.x = packh2(v.x, v.y); o.y = packh2(v.z, v.w);
        d[i] = o;
    }
}

// ---------------- gating: logits + softmax ---------------------------------
__global__ void k_gate(const float* __restrict__ x, const float* __restrict__ gw) {
    int t = blockIdx.x;
    __shared__ float xs[DD];
    __shared__ float lg[EE];
    int tid = threadIdx.x;
    for (int k = tid; k < DD; k += 128) xs[k] = x[(size_t)t * DD + k];
    __syncthreads();
    int w = tid >> 5, lane = tid & 31;
    for (int e = w * 4; e < w * 4 + 4; e++) {
        const float* g = gw + (size_t)e * DD;
        float s = 0.f;
        for (int k = lane; k < DD; k += 32) s += xs[k] * g[k];
        for (int o = 16; o; o >>= 1) s += __shfl_down_sync(0xffffffffu, s, o);
        if (!lane) lg[e] = s;
    }
    __syncthreads();
    if (tid == 0) {
        float m = lg[0];
        for (int e = 1; e < EE; e++) m = fmaxf(m, lg[e]);
        float ex[EE]; float sum = 0.f;
        for (int e = 0; e < EE; e++) { ex[e] = expf(lg[e] - m); sum += ex[e]; }
        float inv = 1.f / sum;
        for (int e = 0; e < EE; e++) g_scores[(size_t)e * TT + t] = ex[e] * inv;
    }
}

// ---------------- per-expert top-C via bitonic sort ------------------------
__global__ void k_topk() {
    int e = blockIdx.x;
    __shared__ float v[TT];
    __shared__ int   ix[TT];
    int tid = threadIdx.x;
    for (int i = tid; i < TT; i += 512) { v[i] = g_scores[(size_t)e * TT + i]; ix[i] = i; }
    __syncthreads();
    for (int k = 2; k <= TT; k <<= 1) {
        for (int j = k >> 1; j > 0; j >>= 1) {
            for (int i = tid; i < TT; i += 512) {
                int p = i ^ j;
                if (p > i) {
                    bool desc = ((i & k) == 0);
                    float a = v[i], b = v[p];
                    if (desc ? (a < b) : (a > b)) {
                        v[i] = b; v[p] = a; int q = ix[i]; ix[i] = ix[p]; ix[p] = q;
                    }
                }
            }
            __syncthreads();
        }
    }
    for (int c = tid; c < CC; c += 512) { g_tidx[e * CC + c] = ix[c]; g_tw[e * CC + c] = v[c]; }
}

// ---------------- gather selected tokens -> fp16 ---------------------------
__global__ void k_gather(const float4* __restrict__ x4) {
    int gid = blockIdx.x * blockDim.x + threadIdx.x;
    if (gid >= EE * CC * (DD / 4)) return;
    int q = gid & (DD / 4 - 1);
    int r = gid >> 8;
    float4 v = x4[(size_t)g_tidx[r] * (DD / 4) + q];
    uint2 o; o.x = packh2(v.x, v.y); o.y = packh2(v.z, v.w);
    reinterpret_cast<uint2*>(g_hxg)[gid] = o;
}

// ---------------- dual NT-GEMM + GELU: A fp16, B fp32 (cvt at frag) --------
// hH = fp16( gelu(A @ Bg^T) * (A @ Bu^T) ).  Block 128x64, warps 2x4 (64x16).
__global__ __launch_bounds__(256, 2) void k_mlp_in_h(
    const __half* __restrict__ A0, const float* __restrict__ Bg0,
    const float* __restrict__ Bu0, __half* __restrict__ H0,
    int M, int N, int K, long sA, long sB, long sH)
{
    extern __shared__ char smraw[];
    __half (*As)[128][HS] = (__half(*)[128][HS])smraw;
    float  (*Gs)[64][FS]  = (float(*)[64][FS])(smraw + 20480);
    float  (*Us)[64][FS]  = (float(*)[64][FS])(smraw + 20480 + 18432);

    int e = blockIdx.z;
    const __half* A  = A0  + (size_t)e * sA;
    const float*  Bg = Bg0 + (size_t)e * sB;
    const float*  Bu = Bu0 + (size_t)e * sB;
    __half*       H  = H0  + (size_t)e * sH;

    int m0 = blockIdx.y * 128, n0 = blockIdx.x * 64;
    int tid = threadIdx.x, lane = tid & 31, warp = tid >> 5;
    int mo = (warp & 1) * 64, no = (warp >> 1) * 16;
    int gg = lane >> 2, tt = lane & 3;

    float accG[4][2][4] = {{{0}}}, accU[4][2][4] = {{{0}}};

    // A: 128 rows x 32 halves = 512 x16B chunks; 2/thread
    int ha0 = tid, ha1 = tid + 256;
    int ar0 = ha0 >> 2, aq0 = (ha0 & 3) * 8;
    int ar1 = ha1 >> 2, aq1 = (ha1 & 3) * 8;
    // G/U: 64 rows x 32 floats = 512 x16B chunks; 2/thread each
    int fb0 = tid, fb1 = tid + 256;
    int gr0 = fb0 >> 3, gq0 = (fb0 & 7) * 4;
    int gr1 = fb1 >> 3, gq1 = (fb1 & 7) * 4;

    int iters = K / BK;

#define STG_IN(slot, k0)                                                          \
    do {                                                                          \
        long _k = (k0);                                                           \
        cpa16(&As[slot][ar0][aq0], A  + (size_t)(m0 + ar0) * K + _k + aq0);       \
        cpa16(&As[slot][ar1][aq1], A  + (size_t)(m0 + ar1) * K + _k + aq1);       \
        cpa16(&Gs[slot][gr0][gq0], Bg + (size_t)(n0 + gr0) * K + _k + gq0);       \
        cpa16(&Gs[slot][gr1][gq1], Bg + (size_t)(n0 + gr1) * K + _k + gq1);       \
        cpa16(&Us[slot][gr0][gq0], Bu + (size_t)(n0 + gr0) * K + _k + gq0);       \
        cpa16(&Us[slot][gr1][gq1], Bu + (size_t)(n0 + gr1) * K + _k + gq1);       \
    } while (0)

    STG_IN(0, 0);
    cpa_commit();

    for (int it = 0; it < iters; it++) {
        int st = it & 1;
        if (it + 1 < iters) STG_IN(1 - st, (long)(it + 1) * BK);
        cpa_commit();
        cpa_wait1();
        __syncthreads();

#pragma unroll
        for (int ks = 0; ks < BK; ks += 16) {
            unsigned af[4][4];
#pragma unroll
            for (int mi = 0; mi < 4; mi++) {
                int r = mo + mi * 16 + gg;
                af[mi][0] = ldh2(&As[st][r][ks + tt * 2]);
                af[mi][1] = ldh2(&As[st][r + 8][ks + tt * 2]);
                af[mi][2] = ldh2(&As[st][r][ks + tt * 2 + 8]);
                af[mi][3] = ldh2(&As[st][r + 8][ks + tt * 2 + 8]);
            }
#pragma unroll
            for (int ni = 0; ni < 2; ni++) {
                int bn = no + ni * 8 + gg;
                float2 g0 = *(float2*)&Gs[st][bn][ks + tt * 2];
                float2 g1 = *(float2*)&Gs[st][bn][ks + tt * 2 + 8];
                float2 u0 = *(float2*)&Us[st][bn][ks + tt * 2];
                float2 u1 = *(float2*)&Us[st][bn][ks + tt * 2 + 8];
                unsigned bg[2] = { packh2(g0.x, g0.y), packh2(g1.x, g1.y) };
                unsigned bu[2] = { packh2(u0.x, u0.y), packh2(u1.x, u1.y) };
#pragma unroll
                for (int mi = 0; mi < 4; mi++) {
                    mma_f16(accG[mi][ni], af[mi], bg, accG[mi][ni]);
                    mma_f16(accU[mi][ni], af[mi], bu, accU[mi][ni]);
                }
            }
        }
        __syncthreads();
    }
#undef STG_IN

    // epilogue: h = fp16(gelu(g) * u)
#pragma unroll
    for (int mi = 0; mi < 4; mi++) {
        int r0 = m0 + mo + mi * 16 + gg;
#pragma unroll
        for (int ni = 0; ni < 2; ni++) {
            int col = n0 + no + ni * 8 + tt * 2;
            unsigned v0 = packh2(gelu_exact(accG[mi][ni][0]) * accU[mi][ni][0],
                                 gelu_exact(accG[mi][ni][1]) * accU[mi][ni][1]);
            unsigned v1 = packh2(gelu_exact(accG[mi][ni][2]) * accU[mi][ni][2],
                                 gelu_exact(accG[mi][ni][3]) * accU[mi][ni][3]);
            *(unsigned*)&H[(size_t)r0 * N + col]       = v0;
            *(unsigned*)&H[(size_t)(r0 + 8) * N + col] = v1;
        }
    }
}

// ---------------- NT-GEMM down-proj: A fp16, B fp32 (cvt at frag) ----------
// Block 128x128, warps 2x4 (64x32). Store or weighted atomic scatter.
__global__ __launch_bounds__(256, 2) void k_mlp_out_h(
    const __half* __restrict__ A0, const float* __restrict__ B0,
    float* __restrict__ out, int M, int N, int K, long sA, long sB,
    const int* __restrict__ tidx, const float* __restrict__ tw)
{
    extern __shared__ char smraw[];
    __half (*As)[128][HS] = (__half(*)[128][HS])smraw;
    float  (*Bs)[128][FS] = (float(*)[128][FS])(smraw + 20480);

    int e = blockIdx.z;
    const __half* A = A0 + (size_t)e * sA;
    const float*  B = B0 + (size_t)e * sB;

    int m0 = blockIdx.y * 128, n0 = blockIdx.x * 128;
    int tid = threadIdx.x, lane = tid & 31, warp = tid >> 5;
    int mo = (warp & 1) * 64, no = (warp >> 1) * 32;
    int gg = lane >> 2, tt = lane & 3;

    float acc[4][4][4] = {{{0}}};

    int ha0 = tid, ha1 = tid + 256;
    int ar0 = ha0 >> 2, aq0 = (ha0 & 3) * 8;
    int ar1 = ha1 >> 2, aq1 = (ha1 & 3) * 8;
    // B: 128 rows x 32 floats = 1024 x16B chunks; 4/thread
    int iters = K / BK;

#define STG_DN(slot, k0)                                                          \
    do {                                                                          \
        long _k = (k0);                                                           \
        cpa16(&As[slot][ar0][aq0], A + (size_t)(m0 + ar0) * K + _k + aq0);        \
        cpa16(&As[slot][ar1][aq1], A + (size_t)(m0 + ar1) * K + _k + aq1);        \
        _Pragma("unroll")                                                         \
        for (int _i = 0; _i < 4; _i++) {                                          \
            int _c = tid + _i * 256;                                              \
            int _r = _c >> 3, _q = (_c & 7) * 4;                                  \
            cpa16(&Bs[slot][_r][_q], B + (size_t)(n0 + _r) * K + _k + _q);        \
        }                                                                         \
    } while (0)

    STG_DN(0, 0);
    cpa_commit();

    for (int it = 0; it < iters; it++) {
        int st = it & 1;
        if (it + 1 < iters) STG_DN(1 - st, (long)(it + 1) * BK);
        cpa_commit();
        cpa_wait1();
        __syncthreads();

#pragma unroll
        for (int ks = 0; ks < BK; ks += 16) {
            unsigned af[4][4];
#pragma unroll
            for (int mi = 0; mi < 4; mi++) {
                int r = mo + mi * 16 + gg;
                af[mi][0] = ldh2(&As[st][r][ks + tt * 2]);
                af[mi][1] = ldh2(&As[st][r + 8][ks + tt * 2]);
                af[mi][2] = ldh2(&As[st][r][ks + tt * 2 + 8]);
                af[mi][3] = ldh2(&As[st][r + 8][ks + tt * 2 + 8]);
            }
#pragma unroll
            for (int ni = 0; ni < 4; ni++) {
                int bn = no + ni * 8 + gg;
                float2 b0 = *(float2*)&Bs[st][bn][ks + tt * 2];
                float2 b1 = *(float2*)&Bs[st][bn][ks + tt * 2 + 8];
                unsigned bf[2] = { packh2(b0.x, b0.y), packh2(b1.x, b1.y) };
#pragma unroll
                for (int mi = 0; mi < 4; mi++)
                    mma_f16(acc[mi][ni], af[mi], bf, acc[mi][ni]);
            }
        }
        __syncthreads();
    }
#undef STG_DN

    if (tidx) {
#pragma unroll
        for (int mi = 0; mi < 4; mi++) {
            int mA = m0 + mo + mi * 16 + gg;
            int mB = mA + 8;
            int tokA = tidx[e * CC + mA]; float wA = tw[e * CC + mA];
            int tokB = tidx[e * CC + mB]; float wB = tw[e * CC + mB];
#pragma unroll
            for (int ni = 0; ni < 4; ni++) {
                int col = n0 + no + ni * 8 + tt * 2;
                atomicAdd(&out[(size_t)tokA * N + col],     acc[mi][ni][0] * wA);
                atomicAdd(&out[(size_t)tokA * N + col + 1], acc[mi][ni][1] * wA);
                atomicAdd(&out[(size_t)tokB * N + col],     acc[mi][ni][2] * wB);
                atomicAdd(&out[(size_t)tokB * N + col + 1], acc[mi][ni][3] * wB);
            }
        }
    } else {
#pragma unroll
        for (int mi = 0; mi < 4; mi++) {
            int r0 = m0 + mo + mi * 16 + gg;
#pragma unroll
            for (int ni = 0; ni < 4; ni++) {
                int col = n0 + no + ni * 8 + tt * 2;
                float* p0 = out + (size_t)r0 * N + col;
                float* p1 = out + (size_t)(r0 + 8) * N + col;
                p0[0] = acc[mi][ni][0]; p0[1] = acc[mi][ni][1];
                p1[0] = acc[mi][ni][2]; p1[1] = acc[mi][ni][3];
            }
        }
    }
}

// ---------------- launch ---------------------------------------------------
extern "C" void kernel_launch(void* const* d_in, const int* in_sizes, int n_in,
                              void* d_out, int out_size) {
    const float* x  = (const float*)d_in[0];
    const float* gw = (const float*)d_in[1];
    const float* Wg = (const float*)d_in[2];
    const float* Wu = (const float*)d_in[3];
    const float* Wd = (const float*)d_in[4];
    const float* Sg = (const float*)d_in[5];
    const float* Su = (const float*)d_in[6];
    const float* Sd = (const float*)d_in[7];
    float* out = (float*)d_out;

    __half *hxg, *hH, *hHs, *hx;
    float* tw; int* tidx;
    cudaGetSymbolAddress((void**)&hxg,  g_hxg);
    cudaGetSymbolAddress((void**)&hH,   g_hH);
    cudaGetSymbolAddress((void**)&hHs,  g_hHs);
    cudaGetSymbolAddress((void**)&hx,   g_hx);
    cudaGetSymbolAddress((void**)&tidx, g_tidx);
    cudaGetSymbolAddress((void**)&tw,   g_tw);

    cudaFuncSetAttribute(k_mlp_in_h,  cudaFuncAttributeMaxDynamicSharedMemorySize, SM_IN_BYTES);
    cudaFuncSetAttribute(k_mlp_out_h, cudaFuncAttributeMaxDynamicSharedMemorySize, SM_DN_BYTES);

    // only x needs an explicit fp16 copy (A-operand of shared gate/up GEMM)
    k_cvt_h<<<512, 256>>>((const float4*)x, (uint2*)hx, TT * DD / 4);

    k_gate<<<TT, 128>>>(x, gw);
    k_topk<<<EE, 512>>>();
    k_gather<<<(EE * CC * (DD / 4) + 255) / 256, 256>>>((const float4*)x);

    // expert gate/up + gelu  (M=C, N=I, K=D), batched over experts
    dim3 g1(II / 64, CC / 128, EE);
    k_mlp_in_h<<<g1, 256, SM_IN_BYTES>>>(hxg, Wg, Wu, hH, CC, II, DD,
                                         (long)CC * DD, (long)II * DD, (long)CC * II);
    // shared gate/up + gelu  (M=T, N=IS, K=D)
    dim3 g2(IIS / 64, TT / 128, 1);
    k_mlp_in_h<<<g2, 256, SM_IN_BYTES>>>(hx, Sg, Su, hHs, TT, IIS, DD, 0, 0, 0);

    // shared down-proj: fully initializes out  (M=T, N=D, K=IS)
    dim3 g3(DD / 128, TT / 128, 1);
    k_mlp_out_h<<<g3, 256, SM_DN_BYTES>>>(hHs, Sd, out, TT, DD, IIS, 0, 0, nullptr, nullptr);
    // expert down-proj + weighted scatter-add  (M=C, N=D, K=I)
    dim3 g4(DD / 128, CC / 128, EE);
    k_mlp_out_h<<<g4, 256, SM_DN_BYTES>>>(hH, Wd, out, CC, DD, II,
                                          (long)CC * II, (long)DD * II, tidx, tw);
}

// round 11
// speedup vs baseline: 1.2700x; 1.2700x over previous
#include <cuda_runtime.h>
#include <cuda_fp16.h>
#include <math.h>
#include <stdint.h>

// Problem constants
#define TT   4096
#define DD   1024
#define EE   16
#define CC   512
#define II   4096
#define IIS  2048

#define BK   64     // k-tile (halves)
#define HS   72     // smem row stride in halves (64 data + 8 pad; conflict-free)

// dynamic smem (bytes): in : As[2][128][72] + Gs[2][64][72] + Us[2][64][72] (fp16)
//                       dn : As[2][128][72] + Bs[2][128][72] (fp16)
#define SM_BYTES 73728

// ---------------- scratch (device globals; no allocs allowed) --------------
__device__ __align__(16) float g_scores[EE * TT];
__device__ int   g_tidx[EE * CC];
__device__ float g_tw  [EE * CC];
__device__ __align__(16) __half g_hxg[(size_t)EE * CC * DD];
__device__ __align__(16) __half g_hH [(size_t)EE * CC * II];
__device__ __align__(16) __half g_hHs[(size_t)TT * IIS];
__device__ __align__(16) __half g_hx [(size_t)TT * DD];
__device__ __align__(16) __half g_hWg[(size_t)EE * II * DD];
__device__ __align__(16) __half g_hWu[(size_t)EE * II * DD];
__device__ __align__(16) __half g_hWd[(size_t)EE * DD * II];
__device__ __align__(16) __half g_hSg[(size_t)IIS * DD];
__device__ __align__(16) __half g_hSu[(size_t)IIS * DD];
__device__ __align__(16) __half g_hSd[(size_t)DD * IIS];

// ---------------- helpers --------------------------------------------------
__device__ __forceinline__ void mma_f16(float* d, const unsigned* a, const unsigned* b,
                                        const float* c) {
    asm volatile(
        "mma.sync.aligned.m16n8k16.row.col.f32.f16.f16.f32 "
        "{%0,%1,%2,%3},{%4,%5,%6,%7},{%8,%9},{%10,%11,%12,%13};"
        : "=f"(d[0]), "=f"(d[1]), "=f"(d[2]), "=f"(d[3])
        : "r"(a[0]), "r"(a[1]), "r"(a[2]), "r"(a[3]),
          "r"(b[0]), "r"(b[1]),
          "f"(c[0]), "f"(c[1]), "f"(c[2]), "f"(c[3]));
}
__device__ __forceinline__ void cpa16(void* dst, const void* src) {
    unsigned s = (unsigned)__cvta_generic_to_shared(dst);
    asm volatile("cp.async.cg.shared.global [%0], [%1], 16;" :: "r"(s), "l"(src));
}
__device__ __forceinline__ void cpa_commit() { asm volatile("cp.async.commit_group;"); }
__device__ __forceinline__ void cpa_wait1()  { asm volatile("cp.async.wait_group 1;"); }

__device__ __forceinline__ unsigned ldh2(const __half* p) { return *(const unsigned*)p; }
__device__ __forceinline__ unsigned packh2(float a, float b) {
    __half2 h = __floats2half2_rn(a, b);
    return *(unsigned*)&h;
}
__device__ __forceinline__ float gelu_exact(float g) {
    return 0.5f * g * (1.f + erff(g * 0.70710678118654752f));
}

// ---------------- fp32 -> fp16 copy ----------------------------------------
__global__ void k_cvt_h(const float4* __restrict__ s, uint2* __restrict__ d, int n4) {
    for (int i = blockIdx.x * blockDim.x + threadIdx.x; i < n4; i += gridDim.x * blockDim.x) {
        float4 v = s[i];
        uint2 o; o.x = packh2(v.x, v.y); o.y = packh2(v.z, v.w);
        d[i] = o;
    }
}

// ---------------- gating: logits + softmax ---------------------------------
__global__ void k_gate(const float* __restrict__ x, const float* __restrict__ gw) {
    int t = blockIdx.x;
    __shared__ float xs[DD];
    __shared__ float lg[EE];
    int tid = threadIdx.x;
    for (int k = tid; k < DD; k += 128) xs[k] = x[(size_t)t * DD + k];
    __syncthreads();
    int w = tid >> 5, lane = tid & 31;
    for (int e = w * 4; e < w * 4 + 4; e++) {
        const float* g = gw + (size_t)e * DD;
        float s = 0.f;
        for (int k = lane; k < DD; k += 32) s += xs[k] * g[k];
        for (int o = 16; o; o >>= 1) s += __shfl_down_sync(0xffffffffu, s, o);
        if (!lane) lg[e] = s;
    }
    __syncthreads();
    if (tid == 0) {
        float m = lg[0];
        for (int e = 1; e < EE; e++) m = fmaxf(m, lg[e]);
        float ex[EE]; float sum = 0.f;
        for (int e = 0; e < EE; e++) { ex[e] = expf(lg[e] - m); sum += ex[e]; }
        float inv = 1.f / sum;
        for (int e = 0; e < EE; e++) g_scores[(size_t)e * TT + t] = ex[e] * inv;
    }
}

// ---------------- per-expert top-C via bitonic sort ------------------------
__global__ void k_topk() {
    int e = blockIdx.x;
    __shared__ float v[TT];
    __shared__ int   ix[TT];
    int tid = threadIdx.x;
    for (int i = tid; i < TT; i += 512) { v[i] = g_scores[(size_t)e * TT + i]; ix[i] = i; }
    __syncthreads();
    for (int k = 2; k <= TT; k <<= 1) {
        for (int j = k >> 1; j > 0; j >>= 1) {
            for (int i = tid; i < TT; i += 512) {
                int p = i ^ j;
                if (p > i) {
                    bool desc = ((i & k) == 0);
                    float a = v[i], b = v[p];
                    if (desc ? (a < b) : (a > b)) {
                        v[i] = b; v[p] = a; int q = ix[i]; ix[i] = ix[p]; ix[p] = q;
                    }
                }
            }
            __syncthreads();
        }
    }
    for (int c = tid; c < CC; c += 512) { g_tidx[e * CC + c] = ix[c]; g_tw[e * CC + c] = v[c]; }
}

// ---------------- gather selected tokens -> fp16 ---------------------------
__global__ void k_gather(const float4* __restrict__ x4) {
    int gid = blockIdx.x * blockDim.x + threadIdx.x;
    if (gid >= EE * CC * (DD / 4)) return;
    int q = gid & (DD / 4 - 1);
    int r = gid >> 8;
    float4 v = x4[(size_t)g_tidx[r] * (DD / 4) + q];
    uint2 o; o.x = packh2(v.x, v.y); o.y = packh2(v.z, v.w);
    reinterpret_cast<uint2*>(g_hxg)[gid] = o;
}

// ---------------- fused dual NT-GEMM + GELU (expert + shared) --------------
// Blocks [0,4096): expert gate/up.  Blocks [4096,5120): shared gate/up.
// Block tile 128x64, warps 2x4 (64x16). K=1024 for both. BK=64.
__global__ __launch_bounds__(256, 2) void k_in_f() {
    extern __shared__ char smraw[];
    __half (*As)[128][HS] = (__half(*)[128][HS])smraw;
    __half (*Gs)[64][HS]  = (__half(*)[64][HS])(smraw + 36864);
    __half (*Us)[64][HS]  = (__half(*)[64][HS])(smraw + 36864 + 18432);

    int bid = blockIdx.x;
    const __half *A, *Bg, *Bu; __half* H;
    int m0, n0, N;
    if (bid < 4096) {               // expert: 256 tiles per expert (4 m x 64 n)
        int e = bid >> 8, t = bid & 255;
        m0 = (t >> 6) * 128; n0 = (t & 63) * 64;
        A  = g_hxg + (size_t)e * CC * DD;
        Bg = g_hWg + (size_t)e * II * DD;
        Bu = g_hWu + (size_t)e * II * DD;
        H  = g_hH  + (size_t)e * CC * II;
        N  = II;
    } else {                        // shared: 32 m x 32 n
        int t = bid - 4096;
        m0 = (t >> 5) * 128; n0 = (t & 31) * 64;
        A = g_hx; Bg = g_hSg; Bu = g_hSu; H = g_hHs; N = IIS;
    }
    const int K = DD;

    int tid = threadIdx.x, lane = tid & 31, warp = tid >> 5;
    int mo = (warp & 1) * 64, no = (warp >> 1) * 16;
    int gg = lane >> 2, tt = lane & 3;

    float accG[4][2][4] = {{{0}}}, accU[4][2][4] = {{{0}}};

    const int iters = K / BK;       // 16

#define STG_IN(slot, k0)                                                         \
    do {                                                                         \
        long _k = (k0);                                                          \
        _Pragma("unroll")                                                        \
        for (int _i = 0; _i < 4; _i++) {                                         \
            int _c = tid + _i * 256, _r = _c >> 3, _q = (_c & 7) * 8;            \
            cpa16(&As[slot][_r][_q], A + (size_t)(m0 + _r) * K + _k + _q);       \
        }                                                                        \
        _Pragma("unroll")                                                        \
        for (int _i = 0; _i < 2; _i++) {                                         \
            int _c = tid + _i * 256, _r = _c >> 3, _q = (_c & 7) * 8;            \
            cpa16(&Gs[slot][_r][_q], Bg + (size_t)(n0 + _r) * K + _k + _q);      \
            cpa16(&Us[slot][_r][_q], Bu + (size_t)(n0 + _r) * K + _k + _q);      \
        }                                                                        \
    } while (0)

    STG_IN(0, 0);
    cpa_commit();

    for (int it = 0; it < iters; it++) {
        int st = it & 1;
        if (it + 1 < iters) STG_IN(1 - st, (long)(it + 1) * BK);
        cpa_commit();
        cpa_wait1();
        __syncthreads();

#pragma unroll
        for (int ks = 0; ks < BK; ks += 16) {
            unsigned af[4][4];
#pragma unroll
            for (int mi = 0; mi < 4; mi++) {
                int r = mo + mi * 16 + gg;
                af[mi][0] = ldh2(&As[st][r][ks + tt * 2]);
                af[mi][1] = ldh2(&As[st][r + 8][ks + tt * 2]);
                af[mi][2] = ldh2(&As[st][r][ks + tt * 2 + 8]);
                af[mi][3] = ldh2(&As[st][r + 8][ks + tt * 2 + 8]);
            }
#pragma unroll
            for (int ni = 0; ni < 2; ni++) {
                int bn = no + ni * 8 + gg;
                unsigned bg[2], bu[2];
                bg[0] = ldh2(&Gs[st][bn][ks + tt * 2]);
                bg[1] = ldh2(&Gs[st][bn][ks + tt * 2 + 8]);
                bu[0] = ldh2(&Us[st][bn][ks + tt * 2]);
                bu[1] = ldh2(&Us[st][bn][ks + tt * 2 + 8]);
#pragma unroll
                for (int mi = 0; mi < 4; mi++) {
                    mma_f16(accG[mi][ni], af[mi], bg, accG[mi][ni]);
                    mma_f16(accU[mi][ni], af[mi], bu, accU[mi][ni]);
                }
            }
        }
        __syncthreads();
    }
#undef STG_IN

#pragma unroll
    for (int mi = 0; mi < 4; mi++) {
        int r0 = m0 + mo + mi * 16 + gg;
#pragma unroll
        for (int ni = 0; ni < 2; ni++) {
            int col = n0 + no + ni * 8 + tt * 2;
            unsigned v0 = packh2(gelu_exact(accG[mi][ni][0]) * accU[mi][ni][0],
                                 gelu_exact(accG[mi][ni][1]) * accU[mi][ni][1]);
            unsigned v1 = packh2(gelu_exact(accG[mi][ni][2]) * accU[mi][ni][2],
                                 gelu_exact(accG[mi][ni][3]) * accU[mi][ni][3]);
            *(unsigned*)&H[(size_t)r0 * N + col]       = v0;
            *(unsigned*)&H[(size_t)(r0 + 8) * N + col] = v1;
        }
    }
}

// ---------------- fused down-proj GEMM (expert scatter + shared) -----------
// Blocks [0,512): expert down (K=II, weighted scatter). [512,768): shared (K=IIS).
// out MUST be zeroed before this kernel; all writes are atomicAdd.
// Block tile 128x128, warps 2x4 (64x32). BK=64.
__global__ __launch_bounds__(256, 2) void k_dn_f(float* __restrict__ out) {
    extern __shared__ char smraw[];
    __half (*As)[128][HS] = (__half(*)[128][HS])smraw;
    __half (*Bs)[128][HS] = (__half(*)[128][HS])(smraw + 36864);

    int bid = blockIdx.x;
    const __half *A, *B;
    int m0, n0, K, e = 0;
    bool scatter;
    if (bid < 512) {                // expert: 32 tiles per expert (4 m x 8 n)
        e = bid >> 5; int t = bid & 31;
        m0 = (t >> 3) * 128; n0 = (t & 7) * 128;
        A = g_hH  + (size_t)e * CC * II;
        B = g_hWd + (size_t)e * DD * II;
        K = II; scatter = true;
    } else {                        // shared: 32 m x 8 n
        int t = bid - 512;
        m0 = (t >> 3) * 128; n0 = (t & 7) * 128;
        A = g_hHs; B = g_hSd; K = IIS; scatter = false;
    }
    const int N = DD;

    int tid = threadIdx.x, lane = tid & 31, warp = tid >> 5;
    int mo = (warp & 1) * 64, no = (warp >> 1) * 32;
    int gg = lane >> 2, tt = lane & 3;

    float acc[4][4][4] = {{{0}}};

    const int iters = K / BK;

#define STG_DN(slot, k0)                                                         \
    do {                                                                         \
        long _k = (k0);                                                          \
        _Pragma("unroll")                                                        \
        for (int _i = 0; _i < 4; _i++) {                                         \
            int _c = tid + _i * 256, _r = _c >> 3, _q = (_c & 7) * 8;            \
            cpa16(&As[slot][_r][_q], A + (size_t)(m0 + _r) * K + _k + _q);       \
            cpa16(&Bs[slot][_r][_q], B + (size_t)(n0 + _r) * K + _k + _q);       \
        }                                                                        \
    } while (0)

    STG_DN(0, 0);
    cpa_commit();

    for (int it = 0; it < iters; it++) {
        int st = it & 1;
        if (it + 1 < iters) STG_DN(1 - st, (long)(it + 1) * BK);
        cpa_commit();
        cpa_wait1();
        __syncthreads();

#pragma unroll
        for (int ks = 0; ks < BK; ks += 16) {
            unsigned af[4][4];
#pragma unroll
            for (int mi = 0; mi < 4; mi++) {
                int r = mo + mi * 16 + gg;
                af[mi][0] = ldh2(&As[st][r][ks + tt * 2]);
                af[mi][1] = ldh2(&As[st][r + 8][ks + tt * 2]);
                af[mi][2] = ldh2(&As[st][r][ks + tt * 2 + 8]);
                af[mi][3] = ldh2(&As[st][r + 8][ks + tt * 2 + 8]);
            }
#pragma unroll
            for (int ni = 0; ni < 4; ni++) {
                int bn = no + ni * 8 + gg;
                unsigned bf[2];
                bf[0] = ldh2(&Bs[st][bn][ks + tt * 2]);
                bf[1] = ldh2(&Bs[st][bn][ks + tt * 2 + 8]);
#pragma unroll
                for (int mi = 0; mi < 4; mi++)
                    mma_f16(acc[mi][ni], af[mi], bf, acc[mi][ni]);
            }
        }
        __syncthreads();
    }
#undef STG_DN

#pragma unroll
    for (int mi = 0; mi < 4; mi++) {
        int mA = m0 + mo + mi * 16 + gg;
        int mB = mA + 8;
        int tokA, tokB; float wA, wB;
        if (scatter) {
            tokA = g_tidx[e * CC + mA]; wA = g_tw[e * CC + mA];
            tokB = g_tidx[e * CC + mB]; wB = g_tw[e * CC + mB];
        } else {
            tokA = mA; wA = 1.f; tokB = mB; wB = 1.f;
        }
#pragma unroll
        for (int ni = 0; ni < 4; ni++) {
            int col = n0 + no + ni * 8 + tt * 2;
            atomicAdd(&out[(size_t)tokA * N + col],     acc[mi][ni][0] * wA);
            atomicAdd(&out[(size_t)tokA * N + col + 1], acc[mi][ni][1] * wA);
            atomicAdd(&out[(size_t)tokB * N + col],     acc[mi][ni][2] * wB);
            atomicAdd(&out[(size_t)tokB * N + col + 1], acc[mi][ni][3] * wB);
        }
    }
}

// ---------------- launch ---------------------------------------------------
extern "C" void kernel_launch(void* const* d_in, const int* in_sizes, int n_in,
                              void* d_out, int out_size) {
    const float* x  = (const float*)d_in[0];
    const float* gw = (const float*)d_in[1];
    const float* Wg = (const float*)d_in[2];
    const float* Wu = (const float*)d_in[3];
    const float* Wd = (const float*)d_in[4];
    const float* Sg = (const float*)d_in[5];
    const float* Su = (const float*)d_in[6];
    const float* Sd = (const float*)d_in[7];
    float* out = (float*)d_out;

    __half *hWg, *hWu, *hWd, *hSg, *hSu, *hSd, *hx;
    cudaGetSymbolAddress((void**)&hWg, g_hWg);
    cudaGetSymbolAddress((void**)&hWu, g_hWu);
    cudaGetSymbolAddress((void**)&hWd, g_hWd);
    cudaGetSymbolAddress((void**)&hSg, g_hSg);
    cudaGetSymbolAddress((void**)&hSu, g_hSu);
    cudaGetSymbolAddress((void**)&hSd, g_hSd);
    cudaGetSymbolAddress((void**)&hx,  g_hx);

    cudaFuncSetAttribute(k_in_f, cudaFuncAttributeMaxDynamicSharedMemorySize, SM_BYTES);
    cudaFuncSetAttribute(k_dn_f, cudaFuncAttributeMaxDynamicSharedMemorySize, SM_BYTES);

    // fp32 -> fp16 weight/x conversions
    k_cvt_h<<<2048, 256>>>((const float4*)Wg, (uint2*)hWg, EE * II * DD / 4);
    k_cvt_h<<<2048, 256>>>((const float4*)Wu, (uint2*)hWu, EE * II * DD / 4);
    k_cvt_h<<<2048, 256>>>((const float4*)Wd, (uint2*)hWd, EE * DD * II / 4);
    k_cvt_h<<<512, 256>>>((const float4*)Sg, (uint2*)hSg, IIS * DD / 4);
    k_cvt_h<<<512, 256>>>((const float4*)Su, (uint2*)hSu, IIS * DD / 4);
    k_cvt_h<<<512, 256>>>((const float4*)Sd, (uint2*)hSd, DD * IIS / 4);
    k_cvt_h<<<512, 256>>>((const float4*)x,  (uint2*)hx,  TT * DD / 4);

    k_gate<<<TT, 128>>>(x, gw);
    k_topk<<<EE, 512>>>();
    k_gather<<<(EE * CC * (DD / 4) + 255) / 256, 256>>>((const float4*)x);

    // zero out (both down-proj segments atomicAdd)
    cudaMemsetAsync(out, 0, (size_t)TT * DD * sizeof(float));

    // fused gate/up GEMMs (expert 4096 blocks + shared 1024 blocks)
    k_in_f<<<5120, 256, SM_BYTES>>>();
    // fused down-proj GEMMs (expert 512 + shared 256)
    k_dn_f<<<768, 256, SM_BYTES>>>(out);
}

// round 12
// speedup vs baseline: 1.3552x; 1.0671x over previous
#include <cuda_runtime.h>
#include <cuda_fp16.h>
#include <math.h>
#include <stdint.h>

// Problem constants
#define TT   4096
#define DD   1024
#define EE   16
#define CC   512
#define II   4096
#define IIS  2048

#define BK   64     // k-tile (halves)
#define HS   72     // smem row stride in halves (64 data + 8 pad; conflict-free)

// dynamic smem (bytes): in : As[2][128][72] + Gs[2][64][72] + Us[2][64][72] (fp16)
//                       dn : As[2][128][72] + Bs[2][128][72] (fp16)
#define SM_BYTES 73728

// ---------------- scratch (device globals; no allocs allowed) --------------
__device__ __align__(16) float g_scores[EE * TT];
__device__ int   g_tidx[EE * CC];
__device__ float g_tw  [EE * CC];
__device__ __align__(16) __half g_hxg[(size_t)EE * CC * DD];
__device__ __align__(16) __half g_hH [(size_t)EE * CC * II];
__device__ __align__(16) __half g_hHs[(size_t)TT * IIS];
__device__ __align__(16) __half g_hx [(size_t)TT * DD];
__device__ __align__(16) __half g_hWg[(size_t)EE * II * DD];
__device__ __align__(16) __half g_hWu[(size_t)EE * II * DD];
__device__ __align__(16) __half g_hWd[(size_t)EE * DD * II];
__device__ __align__(16) __half g_hSg[(size_t)IIS * DD];
__device__ __align__(16) __half g_hSu[(size_t)IIS * DD];
__device__ __align__(16) __half g_hSd[(size_t)DD * IIS];

// ---------------- helpers --------------------------------------------------
__device__ __forceinline__ void mma_f16(float* d, const unsigned* a, const unsigned* b,
                                        const float* c) {
    asm volatile(
        "mma.sync.aligned.m16n8k16.row.col.f32.f16.f16.f32 "
        "{%0,%1,%2,%3},{%4,%5,%6,%7},{%8,%9},{%10,%11,%12,%13};"
        : "=f"(d[0]), "=f"(d[1]), "=f"(d[2]), "=f"(d[3])
        : "r"(a[0]), "r"(a[1]), "r"(a[2]), "r"(a[3]),
          "r"(b[0]), "r"(b[1]),
          "f"(c[0]), "f"(c[1]), "f"(c[2]), "f"(c[3]));
}
__device__ __forceinline__ void cpa16(void* dst, const void* src) {
    unsigned s = (unsigned)__cvta_generic_to_shared(dst);
    asm volatile("cp.async.cg.shared.global [%0], [%1], 16;" :: "r"(s), "l"(src));
}
__device__ __forceinline__ void cpa_commit() { asm volatile("cp.async.commit_group;"); }
__device__ __forceinline__ void cpa_wait1()  { asm volatile("cp.async.wait_group 1;"); }

__device__ __forceinline__ unsigned ldh2(const __half* p) { return *(const unsigned*)p; }
__device__ __forceinline__ unsigned packh2(float a, float b) {
    __half2 h = __floats2half2_rn(a, b);
    return *(unsigned*)&h;
}
__device__ __forceinline__ float gelu_exact(float g) {
    return 0.5f * g * (1.f + erff(g * 0.70710678118654752f));
}

// ---------------- fp32 -> fp16 copy ----------------------------------------
__global__ void k_cvt_h(const float4* __restrict__ s, uint2* __restrict__ d, int n4) {
    for (int i = blockIdx.x * blockDim.x + threadIdx.x; i < n4; i += gridDim.x * blockDim.x) {
        float4 v = s[i];
        uint2 o; o.x = packh2(v.x, v.y); o.y = packh2(v.z, v.w);
        d[i] = o;
    }
}

// ---------------- gating: logits + softmax ---------------------------------
__global__ void k_gate(const float* __restrict__ x, const float* __restrict__ gw) {
    int t = blockIdx.x;
    __shared__ float xs[DD];
    __shared__ float lg[EE];
    int tid = threadIdx.x;
    for (int k = tid; k < DD; k += 128) xs[k] = x[(size_t)t * DD + k];
    __syncthreads();
    int w = tid >> 5, lane = tid & 31;
    for (int e = w * 4; e < w * 4 + 4; e++) {
        const float* g = gw + (size_t)e * DD;
        float s = 0.f;
        for (int k = lane; k < DD; k += 32) s += xs[k] * g[k];
        for (int o = 16; o; o >>= 1) s += __shfl_down_sync(0xffffffffu, s, o);
        if (!lane) lg[e] = s;
    }
    __syncthreads();
    if (tid == 0) {
        float m = lg[0];
        for (int e = 1; e < EE; e++) m = fmaxf(m, lg[e]);
        float ex[EE]; float sum = 0.f;
        for (int e = 0; e < EE; e++) { ex[e] = expf(lg[e] - m); sum += ex[e]; }
        float inv = 1.f / sum;
        for (int e = 0; e < EE; e++) g_scores[(size_t)e * TT + t] = ex[e] * inv;
    }
}

// ---------------- per-expert top-C via bitonic sort ------------------------
__global__ void k_topk() {
    int e = blockIdx.x;
    __shared__ float v[TT];
    __shared__ int   ix[TT];
    int tid = threadIdx.x;
    for (int i = tid; i < TT; i += 512) { v[i] = g_scores[(size_t)e * TT + i]; ix[i] = i; }
    __syncthreads();
    for (int k = 2; k <= TT; k <<= 1) {
        for (int j = k >> 1; j > 0; j >>= 1) {
            for (int i = tid; i < TT; i += 512) {
                int p = i ^ j;
                if (p > i) {
                    bool desc = ((i & k) == 0);
                    float a = v[i], b = v[p];
                    if (desc ? (a < b) : (a > b)) {
                        v[i] = b; v[p] = a; int q = ix[i]; ix[i] = ix[p]; ix[p] = q;
                    }
                }
            }
            __syncthreads();
        }
    }
    for (int c = tid; c < CC; c += 512) { g_tidx[e * CC + c] = ix[c]; g_tw[e * CC + c] = v[c]; }
}

// ---------------- gather selected tokens -> fp16 ---------------------------
__global__ void k_gather(const float4* __restrict__ x4) {
    int gid = blockIdx.x * blockDim.x + threadIdx.x;
    if (gid >= EE * CC * (DD / 4)) return;
    int q = gid & (DD / 4 - 1);
    int r = gid >> 8;
    float4 v = x4[(size_t)g_tidx[r] * (DD / 4) + q];
    uint2 o; o.x = packh2(v.x, v.y); o.y = packh2(v.z, v.w);
    reinterpret_cast<uint2*>(g_hxg)[gid] = o;
}

// ---------------- fused dual NT-GEMM + GELU (expert + shared) --------------
// Blocks [0,4096): expert gate/up.  Blocks [4096,5120): shared gate/up.
// Block tile 128x64, warps 2x4 (64x16). K=1024 for both. BK=64.
__global__ __launch_bounds__(256, 2) void k_in_f() {
    extern __shared__ char smraw[];
    __half (*As)[128][HS] = (__half(*)[128][HS])smraw;
    __half (*Gs)[64][HS]  = (__half(*)[64][HS])(smraw + 36864);
    __half (*Us)[64][HS]  = (__half(*)[64][HS])(smraw + 36864 + 18432);

    int bid = blockIdx.x;
    const __half *A, *Bg, *Bu; __half* H;
    int m0, n0, N;
    if (bid < 4096) {               // expert: 256 tiles per expert (4 m x 64 n)
        int e = bid >> 8, t = bid & 255;
        m0 = (t >> 6) * 128; n0 = (t & 63) * 64;
        A  = g_hxg + (size_t)e * CC * DD;
        Bg = g_hWg + (size_t)e * II * DD;
        Bu = g_hWu + (size_t)e * II * DD;
        H  = g_hH  + (size_t)e * CC * II;
        N  = II;
    } else {                        // shared: 32 m x 32 n
        int t = bid - 4096;
        m0 = (t >> 5) * 128; n0 = (t & 31) * 64;
        A = g_hx; Bg = g_hSg; Bu = g_hSu; H = g_hHs; N = IIS;
    }
    const int K = DD;

    int tid = threadIdx.x, lane = tid & 31, warp = tid >> 5;
    int mo = (warp & 1) * 64, no = (warp >> 1) * 16;
    int gg = lane >> 2, tt = lane & 3;

    float accG[4][2][4] = {{{0}}}, accU[4][2][4] = {{{0}}};

    const int iters = K / BK;       // 16

#define STG_IN(slot, k0)                                                         \
    do {                                                                         \
        long _k = (k0);                                                          \
        _Pragma("unroll")                                                        \
        for (int _i = 0; _i < 4; _i++) {                                         \
            int _c = tid + _i * 256, _r = _c >> 3, _q = (_c & 7) * 8;            \
            cpa16(&As[slot][_r][_q], A + (size_t)(m0 + _r) * K + _k + _q);       \
        }                                                                        \
        _Pragma("unroll")                                                        \
        for (int _i = 0; _i < 2; _i++) {                                         \
            int _c = tid + _i * 256, _r = _c >> 3, _q = (_c & 7) * 8;            \
            cpa16(&Gs[slot][_r][_q], Bg + (size_t)(n0 + _r) * K + _k + _q);      \
            cpa16(&Us[slot][_r][_q], Bu + (size_t)(n0 + _r) * K + _k + _q);      \
        }                                                                        \
    } while (0)

    STG_IN(0, 0);
    cpa_commit();

    for (int it = 0; it < iters; it++) {
        int st = it & 1;
        if (it + 1 < iters) STG_IN(1 - st, (long)(it + 1) * BK);
        cpa_commit();
        cpa_wait1();
        __syncthreads();

#pragma unroll
        for (int ks = 0; ks < BK; ks += 16) {
            unsigned af[4][4];
#pragma unroll
            for (int mi = 0; mi < 4; mi++) {
                int r = mo + mi * 16 + gg;
                af[mi][0] = ldh2(&As[st][r][ks + tt * 2]);
                af[mi][1] = ldh2(&As[st][r + 8][ks + tt * 2]);
                af[mi][2] = ldh2(&As[st][r][ks + tt * 2 + 8]);
                af[mi][3] = ldh2(&As[st][r + 8][ks + tt * 2 + 8]);
            }
#pragma unroll
            for (int ni = 0; ni < 2; ni++) {
                int bn = no + ni * 8 + gg;
                unsigned bg[2], bu[2];
                bg[0] = ldh2(&Gs[st][bn][ks + tt * 2]);
                bg[1] = ldh2(&Gs[st][bn][ks + tt * 2 + 8]);
                bu[0] = ldh2(&Us[st][bn][ks + tt * 2]);
                bu[1] = ldh2(&Us[st][bn][ks + tt * 2 + 8]);
#pragma unroll
                for (int mi = 0; mi < 4; mi++) {
                    mma_f16(accG[mi][ni], af[mi], bg, accG[mi][ni]);
                    mma_f16(accU[mi][ni], af[mi], bu, accU[mi][ni]);
                }
            }
        }
        __syncthreads();
    }
#undef STG_IN

#pragma unroll
    for (int mi = 0; mi < 4; mi++) {
        int r0 = m0 + mo + mi * 16 + gg;
#pragma unroll
        for (int ni = 0; ni < 2; ni++) {
            int col = n0 + no + ni * 8 + tt * 2;
            unsigned v0 = packh2(gelu_exact(accG[mi][ni][0]) * accU[mi][ni][0],
                                 gelu_exact(accG[mi][ni][1]) * accU[mi][ni][1]);
            unsigned v1 = packh2(gelu_exact(accG[mi][ni][2]) * accU[mi][ni][2],
                                 gelu_exact(accG[mi][ni][3]) * accU[mi][ni][3]);
            *(unsigned*)&H[(size_t)r0 * N + col]       = v0;
            *(unsigned*)&H[(size_t)(r0 + 8) * N + col] = v1;
        }
    }
}

// ---------------- fused down-proj GEMM (expert scatter + shared) -----------
// Blocks [0,512): expert down (K=II, weighted scatter). [512,768): shared (K=IIS).
// out MUST be zeroed before this kernel; all writes are atomicAdd.
// Block tile 128x128, warps 2x4 (64x32). BK=64.
__global__ __launch_bounds__(256, 2) void k_dn_f(float* __restrict__ out) {
    extern __shared__ char smraw[];
    __half (*As)[128][HS] = (__half(*)[128][HS])smraw;
    __half (*Bs)[128][HS] = (__half(*)[128][HS])(smraw + 36864);

    int bid = blockIdx.x;
    const __half *A, *B;
    int m0, n0, K, e = 0;
    bool scatter;
    if (bid < 512) {                // expert: 32 tiles per expert (4 m x 8 n)
        e = bid >> 5; int t = bid & 31;
        m0 = (t >> 3) * 128; n0 = (t & 7) * 128;
        A = g_hH  + (size_t)e * CC * II;
        B = g_hWd + (size_t)e * DD * II;
        K = II; scatter = true;
    } else {                        // shared: 32 m x 8 n
        int t = bid - 512;
        m0 = (t >> 3) * 128; n0 = (t & 7) * 128;
        A = g_hHs; B = g_hSd; K = IIS; scatter = false;
    }
    const int N = DD;

    int tid = threadIdx.x, lane = tid & 31, warp = tid >> 5;
    int mo = (warp & 1) * 64, no = (warp >> 1) * 32;
    int gg = lane >> 2, tt = lane & 3;

    float acc[4][4][4] = {{{0}}};

    const int iters = K / BK;

#define STG_DN(slot, k0)                                                         \
    do {                                                                         \
        long _k = (k0);                                                          \
        _Pragma("unroll")                                                        \
        for (int _i = 0; _i < 4; _i++) {                                         \
            int _c = tid + _i * 256, _r = _c >> 3, _q = (_c & 7) * 8;            \
            cpa16(&As[slot][_r][_q], A + (size_t)(m0 + _r) * K + _k + _q);       \
            cpa16(&Bs[slot][_r][_q], B + (size_t)(n0 + _r) * K + _k + _q);       \
        }                                                                        \
    } while (0)

    STG_DN(0, 0);
    cpa_commit();

    for (int it = 0; it < iters; it++) {
        int st = it & 1;
        if (it + 1 < iters) STG_DN(1 - st, (long)(it + 1) * BK);
        cpa_commit();
        cpa_wait1();
        __syncthreads();

#pragma unroll
        for (int ks = 0; ks < BK; ks += 16) {
            unsigned af[4][4];
#pragma unroll
            for (int mi = 0; mi < 4; mi++) {
                int r = mo + mi * 16 + gg;
                af[mi][0] = ldh2(&As[st][r][ks + tt * 2]);
                af[mi][1] = ldh2(&As[st][r + 8][ks + tt * 2]);
                af[mi][2] = ldh2(&As[st][r][ks + tt * 2 + 8]);
                af[mi][3] = ldh2(&As[st][r + 8][ks + tt * 2 + 8]);
            }
#pragma unroll
            for (int ni = 0; ni < 4; ni++) {
                int bn = no + ni * 8 + gg;
                unsigned bf[2];
                bf[0] = ldh2(&Bs[st][bn][ks + tt * 2]);
                bf[1] = ldh2(&Bs[st][bn][ks + tt * 2 + 8]);
#pragma unroll
                for (int mi = 0; mi < 4; mi++)
                    mma_f16(acc[mi][ni], af[mi], bf, acc[mi][ni]);
            }
        }
        __syncthreads();
    }
#undef STG_DN

#pragma unroll
    for (int mi = 0; mi < 4; mi++) {
        int mA = m0 + mo + mi * 16 + gg;
        int mB = mA + 8;
        int tokA, tokB; float wA, wB;
        if (scatter) {
            tokA = g_tidx[e * CC + mA]; wA = g_tw[e * CC + mA];
            tokB = g_tidx[e * CC + mB]; wB = g_tw[e * CC + mB];
        } else {
            tokA = mA; wA = 1.f; tokB = mB; wB = 1.f;
        }
#pragma unroll
        for (int ni = 0; ni < 4; ni++) {
            int col = n0 + no + ni * 8 + tt * 2;
            atomicAdd(&out[(size_t)tokA * N + col],     acc[mi][ni][0] * wA);
            atomicAdd(&out[(size_t)tokA * N + col + 1], acc[mi][ni][1] * wA);
            atomicAdd(&out[(size_t)tokB * N + col],     acc[mi][ni][2] * wB);
            atomicAdd(&out[(size_t)tokB * N + col + 1], acc[mi][ni][3] * wB);
        }
    }
}

// ---------------- launch ---------------------------------------------------
extern "C" void kernel_launch(void* const* d_in, const int* in_sizes, int n_in,
                              void* d_out, int out_size) {
    const float* x  = (const float*)d_in[0];
    const float* gw = (const float*)d_in[1];
    const float* Wg = (const float*)d_in[2];
    const float* Wu = (const float*)d_in[3];
    const float* Wd = (const float*)d_in[4];
    const float* Sg = (const float*)d_in[5];
    const float* Su = (const float*)d_in[6];
    const float* Sd = (const float*)d_in[7];
    float* out = (float*)d_out;

    __half *hWg, *hWu, *hWd, *hSg, *hSu, *hSd, *hx;
    cudaGetSymbolAddress((void**)&hWg, g_hWg);
    cudaGetSymbolAddress((void**)&hWu, g_hWu);
    cudaGetSymbolAddress((void**)&hWd, g_hWd);
    cudaGetSymbolAddress((void**)&hSg, g_hSg);
    cudaGetSymbolAddress((void**)&hSu, g_hSu);
    cudaGetSymbolAddress((void**)&hSd, g_hSd);
    cudaGetSymbolAddress((void**)&hx,  g_hx);

    cudaFuncSetAttribute(k_in_f, cudaFuncAttributeMaxDynamicSharedMemorySize, SM_BYTES);
    cudaFuncSetAttribute(k_dn_f, cudaFuncAttributeMaxDynamicSharedMemorySize, SM_BYTES);

    // one-time resource init (streams/events; no device memory involved)
    static cudaStream_t s1 = nullptr;
    static cudaEvent_t eFork = nullptr, eReady = nullptr, eW2 = nullptr;
    if (!s1) {
        cudaStreamCreateWithFlags(&s1, cudaStreamNonBlocking);
        cudaEventCreateWithFlags(&eFork,  cudaEventDisableTiming);
        cudaEventCreateWithFlags(&eReady, cudaEventDisableTiming);
        cudaEventCreateWithFlags(&eW2,    cudaEventDisableTiming);
    }

    // ---- fork: s1 does the weight conversions, default does gating chain ---
    cudaEventRecord(eFork, 0);
    cudaStreamWaitEvent(s1, eFork, 0);

    // s1 branch: converts needed by k_in_f first, then k_dn_f's weights
    k_cvt_h<<<2048, 256, 0, s1>>>((const float4*)Wg, (uint2*)hWg, EE * II * DD / 4);
    k_cvt_h<<<2048, 256, 0, s1>>>((const float4*)Wu, (uint2*)hWu, EE * II * DD / 4);
    k_cvt_h<<<512, 256, 0, s1>>>((const float4*)Sg, (uint2*)hSg, IIS * DD / 4);
    k_cvt_h<<<512, 256, 0, s1>>>((const float4*)Su, (uint2*)hSu, IIS * DD / 4);
    k_cvt_h<<<512, 256, 0, s1>>>((const float4*)x,  (uint2*)hx,  TT * DD / 4);
    cudaEventRecord(eReady, s1);
    k_cvt_h<<<2048, 256, 0, s1>>>((const float4*)Wd, (uint2*)hWd, EE * DD * II / 4);
    k_cvt_h<<<512, 256, 0, s1>>>((const float4*)Sd, (uint2*)hSd, DD * IIS / 4);
    cudaEventRecord(eW2, s1);

    // default branch: out zero + gating chain
    cudaMemsetAsync(out, 0, (size_t)TT * DD * sizeof(float));
    k_gate<<<TT, 128>>>(x, gw);
    k_topk<<<EE, 512>>>();
    k_gather<<<(EE * CC * (DD / 4) + 255) / 256, 256>>>((const float4*)x);

    // join 1: gate/up GEMM needs hxg + hx + hWg/hWu/hSg/hSu
    cudaStreamWaitEvent(0, eReady, 0);
    k_in_f<<<5120, 256, SM_BYTES>>>();

    // join 2: down-proj needs hWd/hSd (converted in parallel with k_in_f)
    cudaStreamWaitEvent(0, eW2, 0);
    k_dn_f<<<768, 256, SM_BYTES>>>(out);
}

// round 13
// speedup vs baseline: 1.3838x; 1.0211x over previous
#include <cuda_runtime.h>
#include <cuda_fp16.h>
#include <math.h>
#include <stdint.h>

// Problem constants
#define TT   4096
#define DD   1024
#define EE   16
#define CC   512
#define II   4096
#define IIS  2048

#define BK   64     // k-tile (halves)
#define HS   72     // smem row stride in halves (64 data + 8 pad; conflict-free)
#define SM_BYTES 73728

// ---------------- scratch (device globals; no allocs allowed) --------------
__device__ __align__(16) float g_scores[EE * TT];
__device__ int   g_tidx[EE * CC];
__device__ float g_tw  [EE * CC];
__device__ __align__(16) __half g_hxg[(size_t)EE * CC * DD];
__device__ __align__(16) __half g_hH [(size_t)EE * CC * II];
__device__ __align__(16) __half g_hHs[(size_t)TT * IIS];
__device__ __align__(16) __half g_hx [(size_t)TT * DD];
__device__ __align__(16) __half g_hWg[(size_t)EE * II * DD];
__device__ __align__(16) __half g_hWu[(size_t)EE * II * DD];
__device__ __align__(16) __half g_hWd[(size_t)EE * DD * II];
__device__ __align__(16) __half g_hSg[(size_t)IIS * DD];
__device__ __align__(16) __half g_hSu[(size_t)IIS * DD];
__device__ __align__(16) __half g_hSd[(size_t)DD * IIS];

// ---------------- helpers --------------------------------------------------
__device__ __forceinline__ void mma_f16(float* d, const unsigned* a, const unsigned* b,
                                        const float* c) {
    asm volatile(
        "mma.sync.aligned.m16n8k16.row.col.f32.f16.f16.f32 "
        "{%0,%1,%2,%3},{%4,%5,%6,%7},{%8,%9},{%10,%11,%12,%13};"
        : "=f"(d[0]), "=f"(d[1]), "=f"(d[2]), "=f"(d[3])
        : "r"(a[0]), "r"(a[1]), "r"(a[2]), "r"(a[3]),
          "r"(b[0]), "r"(b[1]),
          "f"(c[0]), "f"(c[1]), "f"(c[2]), "f"(c[3]));
}
__device__ __forceinline__ void cpa16(void* dst, const void* src) {
    unsigned s = (unsigned)__cvta_generic_to_shared(dst);
    asm volatile("cp.async.cg.shared.global [%0], [%1], 16;" :: "r"(s), "l"(src));
}
__device__ __forceinline__ void cpa_commit() { asm volatile("cp.async.commit_group;"); }
__device__ __forceinline__ void cpa_wait1()  { asm volatile("cp.async.wait_group 1;"); }

__device__ __forceinline__ unsigned ldh2(const __half* p) { return *(const unsigned*)p; }
__device__ __forceinline__ unsigned packh2(float a, float b) {
    __half2 h = __floats2half2_rn(a, b);
    return *(unsigned*)&h;
}
__device__ __forceinline__ float gelu_exact(float g) {
    return 0.5f * g * (1.f + erff(g * 0.70710678118654752f));
}

// ---------------- fp32 -> fp16 copy ----------------------------------------
__global__ void k_cvt_h(const float4* __restrict__ s, uint2* __restrict__ d, int n4) {
    for (int i = blockIdx.x * blockDim.x + threadIdx.x; i < n4; i += gridDim.x * blockDim.x) {
        float4 v = s[i];
        uint2 o; o.x = packh2(v.x, v.y); o.y = packh2(v.z, v.w);
        d[i] = o;
    }
}

// ---------------- gating: logits + softmax ---------------------------------
__global__ void k_gate(const float* __restrict__ x, const float* __restrict__ gw) {
    int t = blockIdx.x;
    __shared__ float xs[DD];
    __shared__ float lg[EE];
    int tid = threadIdx.x;
    for (int k = tid; k < DD; k += 128) xs[k] = x[(size_t)t * DD + k];
    __syncthreads();
    int w = tid >> 5, lane = tid & 31;
    for (int e = w * 4; e < w * 4 + 4; e++) {
        const float* g = gw + (size_t)e * DD;
        float s = 0.f;
        for (int k = lane; k < DD; k += 32) s += xs[k] * g[k];
        for (int o = 16; o; o >>= 1) s += __shfl_down_sync(0xffffffffu, s, o);
        if (!lane) lg[e] = s;
    }
    __syncthreads();
    if (tid == 0) {
        float m = lg[0];
        for (int e = 1; e < EE; e++) m = fmaxf(m, lg[e]);
        float ex[EE]; float sum = 0.f;
        for (int e = 0; e < EE; e++) { ex[e] = expf(lg[e] - m); sum += ex[e]; }
        float inv = 1.f / sum;
        for (int e = 0; e < EE; e++) g_scores[(size_t)e * TT + t] = ex[e] * inv;
    }
}

// ---------------- per-expert top-C via bitonic sort ------------------------
__global__ void k_topk() {
    int e = blockIdx.x;
    __shared__ float v[TT];
    __shared__ int   ix[TT];
    int tid = threadIdx.x;
    for (int i = tid; i < TT; i += 512) { v[i] = g_scores[(size_t)e * TT + i]; ix[i] = i; }
    __syncthreads();
    for (int k = 2; k <= TT; k <<= 1) {
        for (int j = k >> 1; j > 0; j >>= 1) {
            for (int i = tid; i < TT; i += 512) {
                int p = i ^ j;
                if (p > i) {
                    bool desc = ((i & k) == 0);
                    float a = v[i], b = v[p];
                    if (desc ? (a < b) : (a > b)) {
                        v[i] = b; v[p] = a; int q = ix[i]; ix[i] = ix[p]; ix[p] = q;
                    }
                }
            }
            __syncthreads();
        }
    }
    for (int c = tid; c < CC; c += 512) { g_tidx[e * CC + c] = ix[c]; g_tw[e * CC + c] = v[c]; }
}

// ---------------- gather selected tokens -> fp16 ---------------------------
__global__ void k_gather(const float4* __restrict__ x4) {
    int gid = blockIdx.x * blockDim.x + threadIdx.x;
    if (gid >= EE * CC * (DD / 4)) return;
    int q = gid & (DD / 4 - 1);
    int r = gid >> 8;
    float4 v = x4[(size_t)g_tidx[r] * (DD / 4) + q];
    uint2 o; o.x = packh2(v.x, v.y); o.y = packh2(v.z, v.w);
    reinterpret_cast<uint2*>(g_hxg)[gid] = o;
}

// ---------------- dual NT-GEMM + GELU (expert OR shared path) --------------
// shared_path=0: grid 4096, expert gate/up. shared_path=1: grid 1024, shared.
// Block tile 128x64, warps 2x4 (64x16). K=1024. BK=64.
__global__ __launch_bounds__(256, 2) void k_in_f(int shared_path) {
    extern __shared__ char smraw[];
    __half (*As)[128][HS] = (__half(*)[128][HS])smraw;
    __half (*Gs)[64][HS]  = (__half(*)[64][HS])(smraw + 36864);
    __half (*Us)[64][HS]  = (__half(*)[64][HS])(smraw + 36864 + 18432);

    int bid = blockIdx.x;
    const __half *A, *Bg, *Bu; __half* H;
    int m0, n0, N;
    if (!shared_path) {             // expert: 256 tiles per expert (4 m x 64 n)
        int e = bid >> 8, t = bid & 255;
        m0 = (t >> 6) * 128; n0 = (t & 63) * 64;
        A  = g_hxg + (size_t)e * CC * DD;
        Bg = g_hWg + (size_t)e * II * DD;
        Bu = g_hWu + (size_t)e * II * DD;
        H  = g_hH  + (size_t)e * CC * II;
        N  = II;
    } else {                        // shared: 32 m x 32 n
        m0 = (bid >> 5) * 128; n0 = (bid & 31) * 64;
        A = g_hx; Bg = g_hSg; Bu = g_hSu; H = g_hHs; N = IIS;
    }
    const int K = DD;

    int tid = threadIdx.x, lane = tid & 31, warp = tid >> 5;
    int mo = (warp & 1) * 64, no = (warp >> 1) * 16;
    int gg = lane >> 2, tt = lane & 3;

    float accG[4][2][4] = {{{0}}}, accU[4][2][4] = {{{0}}};

    const int iters = K / BK;       // 16

#define STG_IN(slot, k0)                                                         \
    do {                                                                         \
        long _k = (k0);                                                          \
        _Pragma("unroll")                                                        \
        for (int _i = 0; _i < 4; _i++) {                                         \
            int _c = tid + _i * 256, _r = _c >> 3, _q = (_c & 7) * 8;            \
            cpa16(&As[slot][_r][_q], A + (size_t)(m0 + _r) * K + _k + _q);       \
        }                                                                        \
        _Pragma("unroll")                                                        \
        for (int _i = 0; _i < 2; _i++) {                                         \
            int _c = tid + _i * 256, _r = _c >> 3, _q = (_c & 7) * 8;            \
            cpa16(&Gs[slot][_r][_q], Bg + (size_t)(n0 + _r) * K + _k + _q);      \
            cpa16(&Us[slot][_r][_q], Bu + (size_t)(n0 + _r) * K + _k + _q);      \
        }                                                                        \
    } while (0)

    STG_IN(0, 0);
    cpa_commit();

    for (int it = 0; it < iters; it++) {
        int st = it & 1;
        if (it + 1 < iters) STG_IN(1 - st, (long)(it + 1) * BK);
        cpa_commit();
        cpa_wait1();
        __syncthreads();

#pragma unroll
        for (int ks = 0; ks < BK; ks += 16) {
            unsigned af[4][4];
#pragma unroll
            for (int mi = 0; mi < 4; mi++) {
                int r = mo + mi * 16 + gg;
                af[mi][0] = ldh2(&As[st][r][ks + tt * 2]);
                af[mi][1] = ldh2(&As[st][r + 8][ks + tt * 2]);
                af[mi][2] = ldh2(&As[st][r][ks + tt * 2 + 8]);
                af[mi][3] = ldh2(&As[st][r + 8][ks + tt * 2 + 8]);
            }
#pragma unroll
            for (int ni = 0; ni < 2; ni++) {
                int bn = no + ni * 8 + gg;
                unsigned bg[2], bu[2];
                bg[0] = ldh2(&Gs[st][bn][ks + tt * 2]);
                bg[1] = ldh2(&Gs[st][bn][ks + tt * 2 + 8]);
                bu[0] = ldh2(&Us[st][bn][ks + tt * 2]);
                bu[1] = ldh2(&Us[st][bn][ks + tt * 2 + 8]);
#pragma unroll
                for (int mi = 0; mi < 4; mi++) {
                    mma_f16(accG[mi][ni], af[mi], bg, accG[mi][ni]);
                    mma_f16(accU[mi][ni], af[mi], bu, accU[mi][ni]);
                }
            }
        }
        __syncthreads();
    }
#undef STG_IN

#pragma unroll
    for (int mi = 0; mi < 4; mi++) {
        int r0 = m0 + mo + mi * 16 + gg;
#pragma unroll
        for (int ni = 0; ni < 2; ni++) {
            int col = n0 + no + ni * 8 + tt * 2;
            unsigned v0 = packh2(gelu_exact(accG[mi][ni][0]) * accU[mi][ni][0],
                                 gelu_exact(accG[mi][ni][1]) * accU[mi][ni][1]);
            unsigned v1 = packh2(gelu_exact(accG[mi][ni][2]) * accU[mi][ni][2],
                                 gelu_exact(accG[mi][ni][3]) * accU[mi][ni][3]);
            *(unsigned*)&H[(size_t)r0 * N + col]       = v0;
            *(unsigned*)&H[(size_t)(r0 + 8) * N + col] = v1;
        }
    }
}

// ---------------- down-proj GEMM (expert scatter OR shared) ----------------
// shared_path=0: grid 512, expert (K=II, weighted scatter).
// shared_path=1: grid 256, shared (K=IIS). out zeroed beforehand; all atomicAdd.
__global__ __launch_bounds__(256, 2) void k_dn_f(float* __restrict__ out, int shared_path) {
    extern __shared__ char smraw[];
    __half (*As)[128][HS] = (__half(*)[128][HS])smraw;
    __half (*Bs)[128][HS] = (__half(*)[128][HS])(smraw + 36864);

    int bid = blockIdx.x;
    const __half *A, *B;
    int m0, n0, K, e = 0;
    if (!shared_path) {             // expert: 32 tiles per expert (4 m x 8 n)
        e = bid >> 5; int t = bid & 31;
        m0 = (t >> 3) * 128; n0 = (t & 7) * 128;
        A = g_hH  + (size_t)e * CC * II;
        B = g_hWd + (size_t)e * DD * II;
        K = II;
    } else {                        // shared: 32 m x 8 n
        m0 = (bid >> 3) * 128; n0 = (bid & 7) * 128;
        A = g_hHs; B = g_hSd; K = IIS;
    }
    const int N = DD;

    int tid = threadIdx.x, lane = tid & 31, warp = tid >> 5;
    int mo = (warp & 1) * 64, no = (warp >> 1) * 32;
    int gg = lane >> 2, tt = lane & 3;

    float acc[4][4][4] = {{{0}}};

    const int iters = K / BK;

#define STG_DN(slot, k0)                                                         \
    do {                                                                         \
        long _k = (k0);                                                          \
        _Pragma("unroll")                                                        \
        for (int _i = 0; _i < 4; _i++) {                                         \
            int _c = tid + _i * 256, _r = _c >> 3, _q = (_c & 7) * 8;            \
            cpa16(&As[slot][_r][_q], A + (size_t)(m0 + _r) * K + _k + _q);       \
            cpa16(&Bs[slot][_r][_q], B + (size_t)(n0 + _r) * K + _k + _q);       \
        }                                                                        \
    } while (0)

    STG_DN(0, 0);
    cpa_commit();

    for (int it = 0; it < iters; it++) {
        int st = it & 1;
        if (it + 1 < iters) STG_DN(1 - st, (long)(it + 1) * BK);
        cpa_commit();
        cpa_wait1();
        __syncthreads();

#pragma unroll
        for (int ks = 0; ks < BK; ks += 16) {
            unsigned af[4][4];
#pragma unroll
            for (int mi = 0; mi < 4; mi++) {
                int r = mo + mi * 16 + gg;
                af[mi][0] = ldh2(&As[st][r][ks + tt * 2]);
                af[mi][1] = ldh2(&As[st][r + 8][ks + tt * 2]);
                af[mi][2] = ldh2(&As[st][r][ks + tt * 2 + 8]);
                af[mi][3] = ldh2(&As[st][r + 8][ks + tt * 2 + 8]);
            }
#pragma unroll
            for (int ni = 0; ni < 4; ni++) {
                int bn = no + ni * 8 + gg;
                unsigned bf[2];
                bf[0] = ldh2(&Bs[st][bn][ks + tt * 2]);
                bf[1] = ldh2(&Bs[st][bn][ks + tt * 2 + 8]);
#pragma unroll
                for (int mi = 0; mi < 4; mi++)
                    mma_f16(acc[mi][ni], af[mi], bf, acc[mi][ni]);
            }
        }
        __syncthreads();
    }
#undef STG_DN

#pragma unroll
    for (int mi = 0; mi < 4; mi++) {
        int mA = m0 + mo + mi * 16 + gg;
        int mB = mA + 8;
        int tokA, tokB; float wA, wB;
        if (!shared_path) {
            tokA = g_tidx[e * CC + mA]; wA = g_tw[e * CC + mA];
            tokB = g_tidx[e * CC + mB]; wB = g_tw[e * CC + mB];
        } else {
            tokA = mA; wA = 1.f; tokB = mB; wB = 1.f;
        }
#pragma unroll
        for (int ni = 0; ni < 4; ni++) {
            int col = n0 + no + ni * 8 + tt * 2;
            atomicAdd(&out[(size_t)tokA * N + col],     acc[mi][ni][0] * wA);
            atomicAdd(&out[(size_t)tokA * N + col + 1], acc[mi][ni][1] * wA);
            atomicAdd(&out[(size_t)tokB * N + col],     acc[mi][ni][2] * wB);
            atomicAdd(&out[(size_t)tokB * N + col + 1], acc[mi][ni][3] * wB);
        }
    }
}

// ---------------- launch ---------------------------------------------------
extern "C" void kernel_launch(void* const* d_in, const int* in_sizes, int n_in,
                              void* d_out, int out_size) {
    const float* x  = (const float*)d_in[0];
    const float* gw = (const float*)d_in[1];
    const float* Wg = (const float*)d_in[2];
    const float* Wu = (const float*)d_in[3];
    const float* Wd = (const float*)d_in[4];
    const float* Sg = (const float*)d_in[5];
    const float* Su = (const float*)d_in[6];
    const float* Sd = (const float*)d_in[7];
    float* out = (float*)d_out;

    __half *hWg, *hWu, *hWd, *hSg, *hSu, *hSd, *hx;
    cudaGetSymbolAddress((void**)&hWg, g_hWg);
    cudaGetSymbolAddress((void**)&hWu, g_hWu);
    cudaGetSymbolAddress((void**)&hWd, g_hWd);
    cudaGetSymbolAddress((void**)&hSg, g_hSg);
    cudaGetSymbolAddress((void**)&hSu, g_hSu);
    cudaGetSymbolAddress((void**)&hSd, g_hSd);
    cudaGetSymbolAddress((void**)&hx,  g_hx);

    cudaFuncSetAttribute(k_in_f, cudaFuncAttributeMaxDynamicSharedMemorySize, SM_BYTES);
    cudaFuncSetAttribute(k_dn_f, cudaFuncAttributeMaxDynamicSharedMemorySize, SM_BYTES);

    // one-time resources (streams/events only; no device memory)
    static cudaStream_t s1 = nullptr, s2 = nullptr;
    static cudaEvent_t eFork = nullptr, eS = nullptr, eWgu = nullptr,
                       eSd = nullptr, eWd = nullptr, eZ = nullptr,
                       eShIn = nullptr, eShDn = nullptr;
    if (!s1) {
        cudaStreamCreateWithFlags(&s1, cudaStreamNonBlocking);
        cudaStreamCreateWithFlags(&s2, cudaStreamNonBlocking);
        cudaEventCreateWithFlags(&eFork, cudaEventDisableTiming);
        cudaEventCreateWithFlags(&eS,    cudaEventDisableTiming);
        cudaEventCreateWithFlags(&eWgu,  cudaEventDisableTiming);
        cudaEventCreateWithFlags(&eSd,   cudaEventDisableTiming);
        cudaEventCreateWithFlags(&eWd,   cudaEventDisableTiming);
        cudaEventCreateWithFlags(&eZ,    cudaEventDisableTiming);
        cudaEventCreateWithFlags(&eShIn, cudaEventDisableTiming);
        cudaEventCreateWithFlags(&eShDn, cudaEventDisableTiming);
    }

    // fork
    cudaEventRecord(eFork, 0);
    cudaStreamWaitEvent(s1, eFork, 0);
    cudaStreamWaitEvent(s2, eFork, 0);

    // ---- s1: conversions, ordered by when consumers need them -------------
    k_cvt_h<<<512, 256, 0, s1>>>((const float4*)x,  (uint2*)hx,  TT * DD / 4);
    k_cvt_h<<<512, 256, 0, s1>>>((const float4*)Sg, (uint2*)hSg, IIS * DD / 4);
    k_cvt_h<<<512, 256, 0, s1>>>((const float4*)Su, (uint2*)hSu, IIS * DD / 4);
    cudaEventRecord(eS, s1);                       // shared gate/up inputs ready
    k_cvt_h<<<2048, 256, 0, s1>>>((const float4*)Wg, (uint2*)hWg, EE * II * DD / 4);
    k_cvt_h<<<2048, 256, 0, s1>>>((const float4*)Wu, (uint2*)hWu, EE * II * DD / 4);
    cudaEventRecord(eWgu, s1);                     // expert gate/up weights ready
    k_cvt_h<<<512, 256, 0, s1>>>((const float4*)Sd, (uint2*)hSd, DD * IIS / 4);
    cudaEventRecord(eSd, s1);
    k_cvt_h<<<2048, 256, 0, s1>>>((const float4*)Wd, (uint2*)hWd, EE * DD * II / 4);
    cudaEventRecord(eWd, s1);

    // ---- default: out zero + expert gating chain ---------------------------
    cudaMemsetAsync(out, 0, (size_t)TT * DD * sizeof(float));
    cudaEventRecord(eZ, 0);
    k_gate<<<TT, 128>>>(x, gw);
    k_topk<<<EE, 512>>>();
    k_gather<<<(EE * CC * (DD / 4) + 255) / 256, 256>>>((const float4*)x);

    // ---- s2: shared-expert chain (overlaps Wg/Wu converts + expert GEMM) ---
    cudaStreamWaitEvent(s2, eS, 0);
    k_in_f<<<1024, 256, SM_BYTES, s2>>>(1);        // shared gate/up + gelu
    cudaStreamWaitEvent(s2, eSd, 0);
    cudaStreamWaitEvent(s2, eZ, 0);
    k_dn_f<<<256, 256, SM_BYTES, s2>>>(out, 1);    // shared down-proj (atomic)
    cudaEventRecord(eShDn, s2);

    // ---- default: expert GEMM chain ----------------------------------------
    cudaStreamWaitEvent(0, eWgu, 0);
    k_in_f<<<4096, 256, SM_BYTES>>>(0);            // expert gate/up + gelu
    cudaStreamWaitEvent(0, eWd, 0);
    k_dn_f<<<512, 256, SM_BYTES>>>(out, 0);        // expert down-proj (scatter)

    // join: make default stream the terminal node
    cudaStreamWaitEvent(0, eShDn, 0);
}

// round 14
// speedup vs baseline: 1.4077x; 1.0173x over previous
#include <cuda_runtime.h>
#include <cuda_fp16.h>
#include <math.h>
#include <stdint.h>

// Problem constants
#define TT   4096
#define DD   1024
#define EE   16
#define CC   512
#define II   4096
#define IIS  2048

#define BK   64     // k-tile (halves)
#define HS   72     // smem row stride in halves (64 data + 8 pad; conflict-free)
#define SM_BYTES 73728

// ---------------- scratch (device globals; no allocs allowed) --------------
__device__ __align__(16) float g_scores[EE * TT];
__device__ int   g_tidx[EE * CC];
__device__ float g_tw  [EE * CC];
__device__ __align__(16) __half g_hxg[(size_t)EE * CC * DD];
__device__ __align__(16) __half g_hH [(size_t)EE * CC * II];
__device__ __align__(16) __half g_hHs[(size_t)TT * IIS];
__device__ __align__(16) __half g_hx [(size_t)TT * DD];
__device__ __align__(16) __half g_hWg[(size_t)EE * II * DD];
__device__ __align__(16) __half g_hWu[(size_t)EE * II * DD];
__device__ __align__(16) __half g_hWd[(size_t)EE * DD * II];
__device__ __align__(16) __half g_hSg[(size_t)IIS * DD];
__device__ __align__(16) __half g_hSu[(size_t)IIS * DD];
__device__ __align__(16) __half g_hSd[(size_t)DD * IIS];

// ---------------- helpers --------------------------------------------------
__device__ __forceinline__ void mma_f16(float* d, const unsigned* a, const unsigned* b,
                                        const float* c) {
    asm volatile(
        "mma.sync.aligned.m16n8k16.row.col.f32.f16.f16.f32 "
        "{%0,%1,%2,%3},{%4,%5,%6,%7},{%8,%9},{%10,%11,%12,%13};"
        : "=f"(d[0]), "=f"(d[1]), "=f"(d[2]), "=f"(d[3])
        : "r"(a[0]), "r"(a[1]), "r"(a[2]), "r"(a[3]),
          "r"(b[0]), "r"(b[1]),
          "f"(c[0]), "f"(c[1]), "f"(c[2]), "f"(c[3]));
}
__device__ __forceinline__ void cpa16(void* dst, const void* src) {
    unsigned s = (unsigned)__cvta_generic_to_shared(dst);
    asm volatile("cp.async.cg.shared.global [%0], [%1], 16;" :: "r"(s), "l"(src));
}
__device__ __forceinline__ void cpa_commit() { asm volatile("cp.async.commit_group;"); }
__device__ __forceinline__ void cpa_wait1()  { asm volatile("cp.async.wait_group 1;"); }

__device__ __forceinline__ unsigned ldh2(const __half* p) { return *(const unsigned*)p; }
__device__ __forceinline__ unsigned packh2(float a, float b) {
    __half2 h = __floats2half2_rn(a, b);
    return *(unsigned*)&h;
}
__device__ __forceinline__ float gelu_exact(float g) {
    return 0.5f * g * (1.f + erff(g * 0.70710678118654752f));
}

// ---------------- fp32 -> fp16 copy ----------------------------------------
__global__ void k_cvt_h(const float4* __restrict__ s, uint2* __restrict__ d, int n4) {
    for (int i = blockIdx.x * blockDim.x + threadIdx.x; i < n4; i += gridDim.x * blockDim.x) {
        float4 v = s[i];
        uint2 o; o.x = packh2(v.x, v.y); o.y = packh2(v.z, v.w);
        d[i] = o;
    }
}

// ---------------- gating: logits + softmax ---------------------------------
__global__ void k_gate(const float* __restrict__ x, const float* __restrict__ gw) {
    int t = blockIdx.x;
    __shared__ float xs[DD];
    __shared__ float lg[EE];
    int tid = threadIdx.x;
    for (int k = tid; k < DD; k += 128) xs[k] = x[(size_t)t * DD + k];
    __syncthreads();
    int w = tid >> 5, lane = tid & 31;
    for (int e = w * 4; e < w * 4 + 4; e++) {
        const float* g = gw + (size_t)e * DD;
        float s = 0.f;
        for (int k = lane; k < DD; k += 32) s += xs[k] * g[k];
        for (int o = 16; o; o >>= 1) s += __shfl_down_sync(0xffffffffu, s, o);
        if (!lane) lg[e] = s;
    }
    __syncthreads();
    if (tid == 0) {
        float m = lg[0];
        for (int e = 1; e < EE; e++) m = fmaxf(m, lg[e]);
        float ex[EE]; float sum = 0.f;
        for (int e = 0; e < EE; e++) { ex[e] = expf(lg[e] - m); sum += ex[e]; }
        float inv = 1.f / sum;
        for (int e = 0; e < EE; e++) g_scores[(size_t)e * TT + t] = ex[e] * inv;
    }
}

// ---------------- per-expert top-C via bitonic sort ------------------------
__global__ void k_topk() {
    int e = blockIdx.x;
    __shared__ float v[TT];
    __shared__ int   ix[TT];
    int tid = threadIdx.x;
    for (int i = tid; i < TT; i += 512) { v[i] = g_scores[(size_t)e * TT + i]; ix[i] = i; }
    __syncthreads();
    for (int k = 2; k <= TT; k <<= 1) {
        for (int j = k >> 1; j > 0; j >>= 1) {
            for (int i = tid; i < TT; i += 512) {
                int p = i ^ j;
                if (p > i) {
                    bool desc = ((i & k) == 0);
                    float a = v[i], b = v[p];
                    if (desc ? (a < b) : (a > b)) {
                        v[i] = b; v[p] = a; int q = ix[i]; ix[i] = ix[p]; ix[p] = q;
                    }
                }
            }
            __syncthreads();
        }
    }
    for (int c = tid; c < CC; c += 512) { g_tidx[e * CC + c] = ix[c]; g_tw[e * CC + c] = v[c]; }
}

// ---------------- gather selected tokens -> fp16 ---------------------------
__global__ void k_gather(const float4* __restrict__ x4) {
    int gid = blockIdx.x * blockDim.x + threadIdx.x;
    if (gid >= EE * CC * (DD / 4)) return;
    int q = gid & (DD / 4 - 1);
    int r = gid >> 8;
    float4 v = x4[(size_t)g_tidx[r] * (DD / 4) + q];
    uint2 o; o.x = packh2(v.x, v.y); o.y = packh2(v.z, v.w);
    reinterpret_cast<uint2*>(g_hxg)[gid] = o;
}

// ---------------- dual NT-GEMM + GELU (expert OR shared path) --------------
// shared_path=0: grid 256*nExperts, experts [e0, e0+n). shared_path=1: grid 1024.
// Block tile 128x64, warps 2x4 (64x16). K=1024. BK=64.
__global__ __launch_bounds__(256, 2) void k_in_f(int shared_path, int e0) {
    extern __shared__ char smraw[];
    __half (*As)[128][HS] = (__half(*)[128][HS])smraw;
    __half (*Gs)[64][HS]  = (__half(*)[64][HS])(smraw + 36864);
    __half (*Us)[64][HS]  = (__half(*)[64][HS])(smraw + 36864 + 18432);

    int bid = blockIdx.x;
    const __half *A, *Bg, *Bu; __half* H;
    int m0, n0, N;
    if (!shared_path) {             // expert: 256 tiles per expert (4 m x 64 n)
        int e = e0 + (bid >> 8), t = bid & 255;
        m0 = (t >> 6) * 128; n0 = (t & 63) * 64;
        A  = g_hxg + (size_t)e * CC * DD;
        Bg = g_hWg + (size_t)e * II * DD;
        Bu = g_hWu + (size_t)e * II * DD;
        H  = g_hH  + (size_t)e * CC * II;
        N  = II;
    } else {                        // shared: 32 m x 32 n
        m0 = (bid >> 5) * 128; n0 = (bid & 31) * 64;
        A = g_hx; Bg = g_hSg; Bu = g_hSu; H = g_hHs; N = IIS;
    }
    const int K = DD;

    int tid = threadIdx.x, lane = tid & 31, warp = tid >> 5;
    int mo = (warp & 1) * 64, no = (warp >> 1) * 16;
    int gg = lane >> 2, tt = lane & 3;

    float accG[4][2][4] = {{{0}}}, accU[4][2][4] = {{{0}}};

    const int iters = K / BK;       // 16

#define STG_IN(slot, k0)                                                         \
    do {                                                                         \
        long _k = (k0);                                                          \
        _Pragma("unroll")                                                        \
        for (int _i = 0; _i < 4; _i++) {                                         \
            int _c = tid + _i * 256, _r = _c >> 3, _q = (_c & 7) * 8;            \
            cpa16(&As[slot][_r][_q], A + (size_t)(m0 + _r) * K + _k + _q);       \
        }                                                                        \
        _Pragma("unroll")                                                        \
        for (int _i = 0; _i < 2; _i++) {                                         \
            int _c = tid + _i * 256, _r = _c >> 3, _q = (_c & 7) * 8;            \
            cpa16(&Gs[slot][_r][_q], Bg + (size_t)(n0 + _r) * K + _k + _q);      \
            cpa16(&Us[slot][_r][_q], Bu + (size_t)(n0 + _r) * K + _k + _q);      \
        }                                                                        \
    } while (0)

    STG_IN(0, 0);
    cpa_commit();

    for (int it = 0; it < iters; it++) {
        int st = it & 1;
        if (it + 1 < iters) STG_IN(1 - st, (long)(it + 1) * BK);
        cpa_commit();
        cpa_wait1();
        __syncthreads();

#pragma unroll
        for (int ks = 0; ks < BK; ks += 16) {
            unsigned af[4][4];
#pragma unroll
            for (int mi = 0; mi < 4; mi++) {
                int r = mo + mi * 16 + gg;
                af[mi][0] = ldh2(&As[st][r][ks + tt * 2]);
                af[mi][1] = ldh2(&As[st][r + 8][ks + tt * 2]);
                af[mi][2] = ldh2(&As[st][r][ks + tt * 2 + 8]);
                af[mi][3] = ldh2(&As[st][r + 8][ks + tt * 2 + 8]);
            }
#pragma unroll
            for (int ni = 0; ni < 2; ni++) {
                int bn = no + ni * 8 + gg;
                unsigned bg[2], bu[2];
                bg[0] = ldh2(&Gs[st][bn][ks + tt * 2]);
                bg[1] = ldh2(&Gs[st][bn][ks + tt * 2 + 8]);
                bu[0] = ldh2(&Us[st][bn][ks + tt * 2]);
                bu[1] = ldh2(&Us[st][bn][ks + tt * 2 + 8]);
#pragma unroll
                for (int mi = 0; mi < 4; mi++) {
                    mma_f16(accG[mi][ni], af[mi], bg, accG[mi][ni]);
                    mma_f16(accU[mi][ni], af[mi], bu, accU[mi][ni]);
                }
            }
        }
        __syncthreads();
    }
#undef STG_IN

#pragma unroll
    for (int mi = 0; mi < 4; mi++) {
        int r0 = m0 + mo + mi * 16 + gg;
#pragma unroll
        for (int ni = 0; ni < 2; ni++) {
            int col = n0 + no + ni * 8 + tt * 2;
            unsigned v0 = packh2(gelu_exact(accG[mi][ni][0]) * accU[mi][ni][0],
                                 gelu_exact(accG[mi][ni][1]) * accU[mi][ni][1]);
            unsigned v1 = packh2(gelu_exact(accG[mi][ni][2]) * accU[mi][ni][2],
                                 gelu_exact(accG[mi][ni][3]) * accU[mi][ni][3]);
            *(unsigned*)&H[(size_t)r0 * N + col]       = v0;
            *(unsigned*)&H[(size_t)(r0 + 8) * N + col] = v1;
        }
    }
}

// ---------------- down-proj GEMM (expert scatter OR shared) ----------------
// shared_path=0: grid 32*nExperts, experts [e0, ...). shared_path=1: grid 256.
// out zeroed beforehand; all writes atomicAdd. Block 128x128, warps 2x4.
__global__ __launch_bounds__(256, 2) void k_dn_f(float* __restrict__ out,
                                                 int shared_path, int e0) {
    extern __shared__ char smraw[];
    __half (*As)[128][HS] = (__half(*)[128][HS])smraw;
    __half (*Bs)[128][HS] = (__half(*)[128][HS])(smraw + 36864);

    int bid = blockIdx.x;
    const __half *A, *B;
    int m0, n0, K, e = 0;
    if (!shared_path) {             // expert: 32 tiles per expert (4 m x 8 n)
        e = e0 + (bid >> 5); int t = bid & 31;
        m0 = (t >> 3) * 128; n0 = (t & 7) * 128;
        A = g_hH  + (size_t)e * CC * II;
        B = g_hWd + (size_t)e * DD * II;
        K = II;
    } else {                        // shared: 32 m x 8 n
        m0 = (bid >> 3) * 128; n0 = (bid & 7) * 128;
        A = g_hHs; B = g_hSd; K = IIS;
    }
    const int N = DD;

    int tid = threadIdx.x, lane = tid & 31, warp = tid >> 5;
    int mo = (warp & 1) * 64, no = (warp >> 1) * 32;
    int gg = lane >> 2, tt = lane & 3;

    float acc[4][4][4] = {{{0}}};

    const int iters = K / BK;

#define STG_DN(slot, k0)                                                         \
    do {                                                                         \
        long _k = (k0);                                                          \
        _Pragma("unroll")                                                        \
        for (int _i = 0; _i < 4; _i++) {                                         \
            int _c = tid + _i * 256, _r = _c >> 3, _q = (_c & 7) * 8;            \
            cpa16(&As[slot][_r][_q], A + (size_t)(m0 + _r) * K + _k + _q);       \
            cpa16(&Bs[slot][_r][_q], B + (size_t)(n0 + _r) * K + _k + _q);       \
        }                                                                        \
    } while (0)

    STG_DN(0, 0);
    cpa_commit();

    for (int it = 0; it < iters; it++) {
        int st = it & 1;
        if (it + 1 < iters) STG_DN(1 - st, (long)(it + 1) * BK);
        cpa_commit();
        cpa_wait1();
        __syncthreads();

#pragma unroll
        for (int ks = 0; ks < BK; ks += 16) {
            unsigned af[4][4];
#pragma unroll
            for (int mi = 0; mi < 4; mi++) {
                int r = mo + mi * 16 + gg;
                af[mi][0] = ldh2(&As[st][r][ks + tt * 2]);
                af[mi][1] = ldh2(&As[st][r + 8][ks + tt * 2]);
                af[mi][2] = ldh2(&As[st][r][ks + tt * 2 + 8]);
                af[mi][3] = ldh2(&As[st][r + 8][ks + tt * 2 + 8]);
            }
#pragma unroll
            for (int ni = 0; ni < 4; ni++) {
                int bn = no + ni * 8 + gg;
                unsigned bf[2];
                bf[0] = ldh2(&Bs[st][bn][ks + tt * 2]);
                bf[1] = ldh2(&Bs[st][bn][ks + tt * 2 + 8]);
#pragma unroll
                for (int mi = 0; mi < 4; mi++)
                    mma_f16(acc[mi][ni], af[mi], bf, acc[mi][ni]);
            }
        }
        __syncthreads();
    }
#undef STG_DN

#pragma unroll
    for (int mi = 0; mi < 4; mi++) {
        int mA = m0 + mo + mi * 16 + gg;
        int mB = mA + 8;
        int tokA, tokB; float wA, wB;
        if (!shared_path) {
            tokA = g_tidx[e * CC + mA]; wA = g_tw[e * CC + mA];
            tokB = g_tidx[e * CC + mB]; wB = g_tw[e * CC + mB];
        } else {
            tokA = mA; wA = 1.f; tokB = mB; wB = 1.f;
        }
#pragma unroll
        for (int ni = 0; ni < 4; ni++) {
            int col = n0 + no + ni * 8 + tt * 2;
            atomicAdd(&out[(size_t)tokA * N + col],     acc[mi][ni][0] * wA);
            atomicAdd(&out[(size_t)tokA * N + col + 1], acc[mi][ni][1] * wA);
            atomicAdd(&out[(size_t)tokB * N + col],     acc[mi][ni][2] * wB);
            atomicAdd(&out[(size_t)tokB * N + col + 1], acc[mi][ni][3] * wB);
        }
    }
}

// ---------------- launch ---------------------------------------------------
extern "C" void kernel_launch(void* const* d_in, const int* in_sizes, int n_in,
                              void* d_out, int out_size) {
    const float* x  = (const float*)d_in[0];
    const float* gw = (const float*)d_in[1];
    const float* Wg = (const float*)d_in[2];
    const float* Wu = (const float*)d_in[3];
    const float* Wd = (const float*)d_in[4];
    const float* Sg = (const float*)d_in[5];
    const float* Su = (const float*)d_in[6];
    const float* Sd = (const float*)d_in[7];
    float* out = (float*)d_out;

    __half *hWg, *hWu, *hWd, *hSg, *hSu, *hSd, *hx;
    cudaGetSymbolAddress((void**)&hWg, g_hWg);
    cudaGetSymbolAddress((void**)&hWu, g_hWu);
    cudaGetSymbolAddress((void**)&hWd, g_hWd);
    cudaGetSymbolAddress((void**)&hSg, g_hSg);
    cudaGetSymbolAddress((void**)&hSu, g_hSu);
    cudaGetSymbolAddress((void**)&hSd, g_hSd);
    cudaGetSymbolAddress((void**)&hx,  g_hx);

    cudaFuncSetAttribute(k_in_f, cudaFuncAttributeMaxDynamicSharedMemorySize, SM_BYTES);
    cudaFuncSetAttribute(k_dn_f, cudaFuncAttributeMaxDynamicSharedMemorySize, SM_BYTES);

    // one-time resources (streams/events only; no device memory)
    static cudaStream_t s1 = nullptr, s2 = nullptr, s3 = nullptr;
    static cudaEvent_t eFork = nullptr, eS = nullptr, eW1 = nullptr, eW2 = nullptr,
                       eWd0 = nullptr, eWd1 = nullptr, eSd = nullptr,
                       eZ = nullptr, eG = nullptr, eShDn = nullptr, eX1 = nullptr;
    if (!s1) {
        cudaStreamCreateWithFlags(&s1, cudaStreamNonBlocking);
        cudaStreamCreateWithFlags(&s2, cudaStreamNonBlocking);
        cudaStreamCreateWithFlags(&s3, cudaStreamNonBlocking);
        cudaEventCreateWithFlags(&eFork, cudaEventDisableTiming);
        cudaEventCreateWithFlags(&eS,    cudaEventDisableTiming);
        cudaEventCreateWithFlags(&eW1,   cudaEventDisableTiming);
        cudaEventCreateWithFlags(&eW2,   cudaEventDisableTiming);
        cudaEventCreateWithFlags(&eWd0,  cudaEventDisableTiming);
        cudaEventCreateWithFlags(&eWd1,  cudaEventDisableTiming);
        cudaEventCreateWithFlags(&eSd,   cudaEventDisableTiming);
        cudaEventCreateWithFlags(&eZ,    cudaEventDisableTiming);
        cudaEventCreateWithFlags(&eG,    cudaEventDisableTiming);
        cudaEventCreateWithFlags(&eShDn, cudaEventDisableTiming);
        cudaEventCreateWithFlags(&eX1,   cudaEventDisableTiming);
    }

    const int HE = EE / 2;                       // 8 experts per half
    const int W_HALF4 = HE * II * DD / 4;        // float4 count per Wg/Wu half
    const int WD_HALF4 = HE * DD * II / 4;

    // fork
    cudaEventRecord(eFork, 0);
    cudaStreamWaitEvent(s1, eFork, 0);
    cudaStreamWaitEvent(s2, eFork, 0);
    cudaStreamWaitEvent(s3, eFork, 0);

    // ---- s1: conversions in consumer order ---------------------------------
    k_cvt_h<<<512, 256, 0, s1>>>((const float4*)x,  (uint2*)hx,  TT * DD / 4);
    k_cvt_h<<<512, 256, 0, s1>>>((const float4*)Sg, (uint2*)hSg, IIS * DD / 4);
    k_cvt_h<<<512, 256, 0, s1>>>((const float4*)Su, (uint2*)hSu, IIS * DD / 4);
    cudaEventRecord(eS, s1);                     // shared gate/up inputs ready
    k_cvt_h<<<1024, 256, 0, s1>>>((const float4*)Wg, (uint2*)hWg, W_HALF4);
    k_cvt_h<<<1024, 256, 0, s1>>>((const float4*)Wu, (uint2*)hWu, W_HALF4);
    cudaEventRecord(eW1, s1);                    // experts 0-7 gate/up weights
    k_cvt_h<<<1024, 256, 0, s1>>>((const float4*)Wg + W_HALF4, (uint2*)hWg + W_HALF4, W_HALF4);
    k_cvt_h<<<1024, 256, 0, s1>>>((const float4*)Wu + W_HALF4, (uint2*)hWu + W_HALF4, W_HALF4);
    cudaEventRecord(eW2, s1);                    // experts 8-15 gate/up weights
    k_cvt_h<<<1024, 256, 0, s1>>>((const float4*)Wd, (uint2*)hWd, WD_HALF4);
    cudaEventRecord(eWd0, s1);                   // experts 0-7 down weights
    k_cvt_h<<<1024, 256, 0, s1>>>((const float4*)Wd + WD_HALF4, (uint2*)hWd + WD_HALF4, WD_HALF4);
    cudaEventRecord(eWd1, s1);                   // experts 8-15 down weights
    k_cvt_h<<<512, 256, 0, s1>>>((const float4*)Sd, (uint2*)hSd, DD * IIS / 4);
    cudaEventRecord(eSd, s1);

    // ---- default: out zero + gating chain ----------------------------------
    cudaMemsetAsync(out, 0, (size_t)TT * DD * sizeof(float));
    cudaEventRecord(eZ, 0);
    k_gate<<<TT, 128>>>(x, gw);
    k_topk<<<EE, 512>>>();
    k_gather<<<(EE * CC * (DD / 4) + 255) / 256, 256>>>((const float4*)x);
    cudaEventRecord(eG, 0);

    // ---- s2: shared-expert chain -------------------------------------------
    cudaStreamWaitEvent(s2, eS, 0);
    k_in_f<<<1024, 256, SM_BYTES, s2>>>(1, 0);       // shared gate/up + gelu
    cudaStreamWaitEvent(s2, eSd, 0);
    cudaStreamWaitEvent(s2, eZ, 0);
    k_dn_f<<<256, 256, SM_BYTES, s2>>>(out, 1, 0);   // shared down-proj
    cudaEventRecord(eShDn, s2);

    // ---- default: expert half 0 (experts 0-7) ------------------------------
    cudaStreamWaitEvent(0, eW1, 0);
    k_in_f<<<2048, 256, SM_BYTES>>>(0, 0);           // expert gate/up 0-7
    cudaStreamWaitEvent(0, eWd0, 0);
    k_dn_f<<<256, 256, SM_BYTES>>>(out, 0, 0);       // expert down 0-7

    // ---- s3: expert half 1 (experts 8-15) ----------------------------------
    cudaStreamWaitEvent(s3, eG, 0);
    cudaStreamWaitEvent(s3, eW2, 0);
    k_in_f<<<2048, 256, SM_BYTES, s3>>>(0, HE);      // expert gate/up 8-15
    cudaStreamWaitEvent(s3, eWd1, 0);
    cudaStreamWaitEvent(s3, eZ, 0);
    k_dn_f<<<256, 256, SM_BYTES, s3>>>(out, 0, HE);  // expert down 8-15
    cudaEventRecord(eX1, s3);

    // join: default stream is the terminal node
    cudaStreamWaitEvent(0, eX1, 0);
    cudaStreamWaitEvent(0, eShDn, 0);
}